// round 10
// baseline (speedup 1.0000x reference)
#include <cuda_runtime.h>
#include <cuda_bf16.h>

#define NND 100000
#define NE  1600000
#define NG  128
#define DD  128
#define OUTD 64
#define NL  4
#define BN_EPS 1e-5f
#define NT  782                    // ceil(NND/128)
#define AST 132                    // smem row stride in bf16 elems

// ---------------- scratch (device globals; no allocation) ----------------
__device__ float g_Z[NND * DD];     // GEMM1 output
__device__ float g_Z2[NND * DD];    // GEMM2 output
__device__ float g_stats[2][2 * DD];
__device__ float g_pg[(NL + 1) * NG * DD];
__device__ int   g_deg[NND];
__device__ int   g_off[NND + 1];
__device__ int   g_cur[NND];
__device__ int   g_esrt[NE];

// ---------------- helpers ----------------
__device__ __forceinline__ void red_add_v4(float* addr, float4 v) {
    asm volatile("red.global.add.v4.f32 [%0], {%1, %2, %3, %4};"
                 :: "l"(addr), "f"(v.x), "f"(v.y), "f"(v.z), "f"(v.w) : "memory");
}
__device__ __forceinline__ unsigned cvt2bf(float lo, float hi) {
    unsigned r;
    asm("cvt.rn.bf16x2.f32 %0, %1, %2;" : "=r"(r) : "f"(hi), "f"(lo));
    return r;
}
__device__ __forceinline__ void mma16816(float* c, const unsigned* a, const unsigned* b) {
    asm volatile("mma.sync.aligned.m16n8k16.row.col.f32.bf16.bf16.f32 "
                 "{%0,%1,%2,%3}, {%4,%5,%6,%7}, {%8,%9}, {%0,%1,%2,%3};"
                 : "+f"(c[0]), "+f"(c[1]), "+f"(c[2]), "+f"(c[3])
                 : "r"(a[0]), "r"(a[1]), "r"(a[2]), "r"(a[3]), "r"(b[0]), "r"(b[1]));
}
__device__ __forceinline__ void cpasync16(unsigned saddr, const void* g, int sz) {
    asm volatile("cp.async.cg.shared.global [%0], [%1], 16, %2;"
                 :: "r"(saddr), "l"(g), "r"(sz) : "memory");
}
#define CP_COMMIT() asm volatile("cp.async.commit_group;" ::: "memory")
#define CP_WAIT0()  asm volatile("cp.async.wait_group 0;" ::: "memory")

// ---------------- CSR build ----------------
__global__ void k_hist(const int* __restrict__ dst) {
    int e = blockIdx.x * blockDim.x + threadIdx.x;
    if (e < NE) atomicAdd(&g_deg[__ldg(&dst[e])], 1);
}
__global__ void k_scan() {
    __shared__ int sp[1024];
    int t = threadIdx.x;
    int base = t * 98;
    int s = 0;
    for (int i = 0; i < 98; i++) { int j = base + i; if (j < NND) s += g_deg[j]; }
    sp[t] = s;
    __syncthreads();
    for (int o = 1; o < 1024; o <<= 1) {
        int v = (t >= o) ? sp[t - o] : 0;
        __syncthreads();
        sp[t] += v;
        __syncthreads();
    }
    int run = t ? sp[t - 1] : 0;
    for (int i = 0; i < 98; i++) {
        int j = base + i;
        if (j < NND) { g_off[j] = run; g_cur[j] = run; run += g_deg[j]; }
    }
    if (t == 0) g_off[NND] = NE;
}
__global__ void k_scatter(const int* __restrict__ src, const int* __restrict__ dst) {
    int e = blockIdx.x * blockDim.x + threadIdx.x;
    if (e >= NE) return;
    int pos = atomicAdd(&g_cur[__ldg(&dst[e])], 1);
    g_esrt[pos] = __ldg(&src[e]);
}

// ======== fused gather-GEMM1: A = (1+eps)h + CSR-sum(h) built in-kernel ========
// h[r] = doBN ? relu(Hs[r]*sc+sh) : Hs[r].  Z = A @ W + bias, output stats fused.
__global__ void __launch_bounds__(512, 1)
k_mmagg(float* __restrict__ Z, const float* __restrict__ Hs,
        const float* __restrict__ W, const float* __restrict__ bias,
        const float* __restrict__ gam, const float* __restrict__ bet,
        const float* __restrict__ statsIn, const float* __restrict__ eps, int l,
        float* __restrict__ statsOut) {
    extern __shared__ unsigned short sm[];
    unsigned short* Whi = sm;
    unsigned short* Wlo = sm + DD * AST;
    unsigned short* Ahi = sm + 2 * DD * AST;
    unsigned short* Alo = sm + 3 * DD * AST;
    __shared__ float colsum[DD], colsq[DD], bias_s[DD], scA[DD], shA[DD];

    const int t = threadIdx.x;
    const int w = t >> 5, lane = t & 31;
    const int g = lane >> 2, q = lane & 3;
    const int wr = (w & 3) * 32;          // MMA: warp rows
    const int wc = (w >> 2) * 32;         // MMA: warp cols (16 warps: 4x4)
    const bool doBN = (gam != nullptr);
    const int ch = lane * 4;

    // prologue
    for (int e2 = t; e2 < DD * DD; e2 += 512) {
        int k = e2 >> 7, n = e2 & 127;
        float x = __ldg(&W[k * DD + n]);
        unsigned xu = __float_as_uint(x);
        Whi[n * AST + k] = (unsigned short)(xu >> 16);
        unsigned lp = cvt2bf(x - __uint_as_float(xu & 0xffff0000u), 0.f);
        Wlo[n * AST + k] = (unsigned short)(lp & 0xffff);
    }
    if (t < DD) {
        colsum[t] = 0.f; colsq[t] = 0.f; bias_s[t] = __ldg(&bias[t]);
        if (doBN) {
            const float inv_n = 1.0f / (float)NND;
            float mu = statsIn[t] * inv_n;
            float var = statsIn[DD + t] * inv_n - mu * mu;
            float s = __ldg(&gam[t]) * rsqrtf(var + BN_EPS);
            scA[t] = s;
            shA[t] = __ldg(&bet[t]) - mu * s;
        }
    }
    __syncthreads();

    float b0c = 1.f, b1c = 1.f, b2c = 1.f, b3c = 1.f;
    float s0c = 0.f, s1c = 0.f, s2c = 0.f, s3c = 0.f;
    if (doBN) {
        b0c = scA[ch]; b1c = scA[ch + 1]; b2c = scA[ch + 2]; b3c = scA[ch + 3];
        s0c = shA[ch]; s1c = shA[ch + 1]; s2c = shA[ch + 2]; s3c = shA[ch + 3];
    }
    const float ev = 1.0f + __ldg(&eps[l]);

#define BN4(v) do { if (doBN) { \
        (v).x = fmaxf((v).x * b0c + s0c, 0.f); (v).y = fmaxf((v).y * b1c + s1c, 0.f); \
        (v).z = fmaxf((v).z * b2c + s2c, 0.f); (v).w = fmaxf((v).w * b3c + s3c, 0.f); } } while (0)

    for (int ti = blockIdx.x; ti < NT; ti += gridDim.x) {
        __syncthreads();   // previous MMA reads of A done

        // gather phase: warp builds rows w*8 .. w*8+7
        for (int rr = 0; rr < 8; rr++) {
            int row = w * 8 + rr;
            int grow = ti * 128 + row;
            float4 acc = make_float4(0.f, 0.f, 0.f, 0.f);
            if (grow < NND) {
                float4 v = __ldg((const float4*)(Hs + (size_t)grow * DD + ch));
                BN4(v);
                acc = make_float4(v.x * ev, v.y * ev, v.z * ev, v.w * ev);
                int e0 = __ldg(&g_off[grow]), e1 = __ldg(&g_off[grow + 1]);
                int i = e0;
                for (; i + 3 < e1; i += 4) {
                    int x0 = __ldg(&g_esrt[i]),     x1 = __ldg(&g_esrt[i + 1]);
                    int x2 = __ldg(&g_esrt[i + 2]), x3 = __ldg(&g_esrt[i + 3]);
                    float4 a0 = __ldg((const float4*)(Hs + (size_t)x0 * DD + ch));
                    float4 a1 = __ldg((const float4*)(Hs + (size_t)x1 * DD + ch));
                    float4 a2 = __ldg((const float4*)(Hs + (size_t)x2 * DD + ch));
                    float4 a3 = __ldg((const float4*)(Hs + (size_t)x3 * DD + ch));
                    BN4(a0); BN4(a1); BN4(a2); BN4(a3);
                    acc.x += (a0.x + a1.x) + (a2.x + a3.x);
                    acc.y += (a0.y + a1.y) + (a2.y + a3.y);
                    acc.z += (a0.z + a1.z) + (a2.z + a3.z);
                    acc.w += (a0.w + a1.w) + (a2.w + a3.w);
                }
                for (; i < e1; i++) {
                    int x0 = __ldg(&g_esrt[i]);
                    float4 a0 = __ldg((const float4*)(Hs + (size_t)x0 * DD + ch));
                    BN4(a0);
                    acc.x += a0.x; acc.y += a0.y; acc.z += a0.z; acc.w += a0.w;
                }
            }
            unsigned hx = __byte_perm(__float_as_uint(acc.x), __float_as_uint(acc.y), 0x7632);
            unsigned hy = __byte_perm(__float_as_uint(acc.z), __float_as_uint(acc.w), 0x7632);
            unsigned lx = cvt2bf(acc.x - __uint_as_float(__float_as_uint(acc.x) & 0xffff0000u),
                                 acc.y - __uint_as_float(__float_as_uint(acc.y) & 0xffff0000u));
            unsigned ly = cvt2bf(acc.z - __uint_as_float(__float_as_uint(acc.z) & 0xffff0000u),
                                 acc.w - __uint_as_float(__float_as_uint(acc.w) & 0xffff0000u));
            *(uint2*)&Ahi[row * AST + ch] = make_uint2(hx, hy);
            *(uint2*)&Alo[row * AST + ch] = make_uint2(lx, ly);
        }
        __syncthreads();   // A ready

        // MMA: 2 m-tiles x 4 n-tiles per warp
        float c[8][4];
#pragma unroll
        for (int i = 0; i < 8; i++)
#pragma unroll
            for (int j = 0; j < 4; j++) c[i][j] = 0.f;

#pragma unroll
        for (int ks = 0; ks < 8; ks++) {
            int k0 = ks * 16;
            unsigned ah[2][4], al[2][4];
#pragma unroll
            for (int m = 0; m < 2; m++) {
                int r0 = wr + m * 16;
                ah[m][0] = *(unsigned*)&Ahi[(r0 + g) * AST + k0 + q * 2];
                ah[m][1] = *(unsigned*)&Ahi[(r0 + g + 8) * AST + k0 + q * 2];
                ah[m][2] = *(unsigned*)&Ahi[(r0 + g) * AST + k0 + 8 + q * 2];
                ah[m][3] = *(unsigned*)&Ahi[(r0 + g + 8) * AST + k0 + 8 + q * 2];
                al[m][0] = *(unsigned*)&Alo[(r0 + g) * AST + k0 + q * 2];
                al[m][1] = *(unsigned*)&Alo[(r0 + g + 8) * AST + k0 + q * 2];
                al[m][2] = *(unsigned*)&Alo[(r0 + g) * AST + k0 + 8 + q * 2];
                al[m][3] = *(unsigned*)&Alo[(r0 + g + 8) * AST + k0 + 8 + q * 2];
            }
            unsigned bh[4][2], bl[4][2];
#pragma unroll
            for (int n = 0; n < 4; n++) {
                int n0 = wc + n * 8 + g;
                bh[n][0] = *(unsigned*)&Whi[n0 * AST + k0 + q * 2];
                bh[n][1] = *(unsigned*)&Whi[n0 * AST + k0 + 8 + q * 2];
                bl[n][0] = *(unsigned*)&Wlo[n0 * AST + k0 + q * 2];
                bl[n][1] = *(unsigned*)&Wlo[n0 * AST + k0 + 8 + q * 2];
            }
#pragma unroll
            for (int m = 0; m < 2; m++)
#pragma unroll
                for (int n = 0; n < 4; n++) {
                    mma16816(c[m * 4 + n], ah[m], bh[n]);
                    mma16816(c[m * 4 + n], al[m], bh[n]);
                    mma16816(c[m * 4 + n], ah[m], bl[n]);
                }
        }

        // epilogue
#pragma unroll
        for (int n = 0; n < 4; n++) {
            int col = wc + n * 8 + q * 2;
            float b0 = bias_s[col], b1 = bias_s[col + 1];
            float s0 = 0.f, s1 = 0.f, q0 = 0.f, q1 = 0.f;
#pragma unroll
            for (int m = 0; m < 2; m++) {
                int row0 = ti * 128 + wr + m * 16 + g;
                float* cf = c[m * 4 + n];
                float v0 = cf[0] + b0, v1 = cf[1] + b1;
                float v2 = cf[2] + b0, v3 = cf[3] + b1;
                if (row0 < NND) {
                    *(float2*)&Z[(size_t)row0 * DD + col] = make_float2(v0, v1);
                    s0 += v0; s1 += v1; q0 += v0 * v0; q1 += v1 * v1;
                }
                if (row0 + 8 < NND) {
                    *(float2*)&Z[(size_t)(row0 + 8) * DD + col] = make_float2(v2, v3);
                    s0 += v2; s1 += v3; q0 += v2 * v2; q1 += v3 * v3;
                }
            }
#pragma unroll
            for (int o = 4; o < 32; o <<= 1) {
                s0 += __shfl_xor_sync(0xffffffffu, s0, o);
                s1 += __shfl_xor_sync(0xffffffffu, s1, o);
                q0 += __shfl_xor_sync(0xffffffffu, q0, o);
                q1 += __shfl_xor_sync(0xffffffffu, q1, o);
            }
            if (lane < 4) {
                atomicAdd(&colsum[col], s0);
                atomicAdd(&colsum[col + 1], s1);
                atomicAdd(&colsq[col], q0);
                atomicAdd(&colsq[col + 1], q1);
            }
        }
    }
#undef BN4

    __syncthreads();
    if (t < DD) {
        atomicAdd(&statsOut[t], colsum[t]);
        atomicAdd(&statsOut[DD + t], colsq[t]);
    }
}

// ---------------- HMMA bf16x3 GEMM2, cp.async-staged, fused stats & input-BN ----------
__global__ void __launch_bounds__(256, 1)
k_mm(float* __restrict__ Z, const float* __restrict__ A,
     const float* __restrict__ W, const float* __restrict__ bias,
     const float* __restrict__ gam, const float* __restrict__ bet,
     const float* __restrict__ statsIn, float* __restrict__ statsOut) {
    extern __shared__ unsigned short sm[];
    unsigned short* Whi = sm;
    unsigned short* Wlo = sm + DD * AST;
    unsigned short* Ahi = sm + 2 * DD * AST;
    unsigned short* Alo = sm + 3 * DD * AST;
    float* Sg = (float*)(sm + 4 * DD * AST);
    __shared__ float colsum[DD], colsq[DD], bias_s[DD], scA[DD], shA[DD];

    const int t = threadIdx.x;
    const int w = t >> 5, lane = t & 31;
    const int g = lane >> 2, q = lane & 3;
    const int wr = (w & 3) * 32;
    const int wc = (w >> 2) * 64;
    const bool doBN = (gam != nullptr);
    const unsigned sgBase = (unsigned)__cvta_generic_to_shared(Sg);

    {
        int ti = blockIdx.x;
#pragma unroll
        for (int i = 0; i < 16; i++) {
            int fi = t + i * 256;
            int row = fi >> 5, kq = fi & 31;
            int grow = ti * 128 + row;
            bool valid = grow < NND;
            const float4* gp = (const float4*)A + ((size_t)(valid ? grow : 0) * 32 + kq);
            cpasync16(sgBase + fi * 16, gp, valid ? 16 : 0);
        }
        CP_COMMIT();
    }

    for (int e = t; e < DD * DD; e += 256) {
        int k = e >> 7, n = e & 127;
        float x = __ldg(&W[k * DD + n]);
        unsigned xu = __float_as_uint(x);
        Whi[n * AST + k] = (unsigned short)(xu >> 16);
        unsigned lp = cvt2bf(x - __uint_as_float(xu & 0xffff0000u), 0.f);
        Wlo[n * AST + k] = (unsigned short)(lp & 0xffff);
    }
    if (t < DD) {
        colsum[t] = 0.f; colsq[t] = 0.f; bias_s[t] = __ldg(&bias[t]);
        if (doBN) {
            const float inv_n = 1.0f / (float)NND;
            float mu = statsIn[t] * inv_n;
            float var = statsIn[DD + t] * inv_n - mu * mu;
            float s = __ldg(&gam[t]) * rsqrtf(var + BN_EPS);
            scA[t] = s;
            shA[t] = __ldg(&bet[t]) - mu * s;
        }
    }

    for (int ti = blockIdx.x; ti < NT; ti += gridDim.x) {
        CP_WAIT0();
        __syncthreads();

#pragma unroll
        for (int i = 0; i < 16; i++) {
            int fi = t + i * 256;
            int row = fi >> 5, kq = fi & 31;
            float4 v = ((const float4*)Sg)[fi];
            if (doBN) {
                int ch = kq * 4;
                v.x = fmaxf(v.x * scA[ch] + shA[ch], 0.f);
                v.y = fmaxf(v.y * scA[ch + 1] + shA[ch + 1], 0.f);
                v.z = fmaxf(v.z * scA[ch + 2] + shA[ch + 2], 0.f);
                v.w = fmaxf(v.w * scA[ch + 3] + shA[ch + 3], 0.f);
            }
            unsigned hx = __byte_perm(__float_as_uint(v.x), __float_as_uint(v.y), 0x7632);
            unsigned hy = __byte_perm(__float_as_uint(v.z), __float_as_uint(v.w), 0x7632);
            unsigned lx = cvt2bf(v.x - __uint_as_float(__float_as_uint(v.x) & 0xffff0000u),
                                 v.y - __uint_as_float(__float_as_uint(v.y) & 0xffff0000u));
            unsigned ly = cvt2bf(v.z - __uint_as_float(__float_as_uint(v.z) & 0xffff0000u),
                                 v.w - __uint_as_float(__float_as_uint(v.w) & 0xffff0000u));
            *(uint2*)&Ahi[row * AST + kq * 4] = make_uint2(hx, hy);
            *(uint2*)&Alo[row * AST + kq * 4] = make_uint2(lx, ly);
        }
        __syncthreads();

        int tn = ti + gridDim.x;
        if (tn < NT) {
#pragma unroll
            for (int i = 0; i < 16; i++) {
                int fi = t + i * 256;
                int row = fi >> 5, kq = fi & 31;
                int grow = tn * 128 + row;
                bool valid = grow < NND;
                const float4* gp = (const float4*)A + ((size_t)(valid ? grow : 0) * 32 + kq);
                cpasync16(sgBase + fi * 16, gp, valid ? 16 : 0);
            }
            CP_COMMIT();
        }

        float c[16][4];
#pragma unroll
        for (int i = 0; i < 16; i++)
#pragma unroll
            for (int j = 0; j < 4; j++) c[i][j] = 0.f;

#pragma unroll
        for (int ks = 0; ks < 8; ks++) {
            int k0 = ks * 16;
            unsigned ah[2][4], al[2][4];
#pragma unroll
            for (int m = 0; m < 2; m++) {
                int r0 = wr + m * 16;
                ah[m][0] = *(unsigned*)&Ahi[(r0 + g) * AST + k0 + q * 2];
                ah[m][1] = *(unsigned*)&Ahi[(r0 + g + 8) * AST + k0 + q * 2];
                ah[m][2] = *(unsigned*)&Ahi[(r0 + g) * AST + k0 + 8 + q * 2];
                ah[m][3] = *(unsigned*)&Ahi[(r0 + g + 8) * AST + k0 + 8 + q * 2];
                al[m][0] = *(unsigned*)&Alo[(r0 + g) * AST + k0 + q * 2];
                al[m][1] = *(unsigned*)&Alo[(r0 + g + 8) * AST + k0 + q * 2];
                al[m][2] = *(unsigned*)&Alo[(r0 + g) * AST + k0 + 8 + q * 2];
                al[m][3] = *(unsigned*)&Alo[(r0 + g + 8) * AST + k0 + 8 + q * 2];
            }
            unsigned bh[8][2], bl[8][2];
#pragma unroll
            for (int n = 0; n < 8; n++) {
                int n0 = wc + n * 8 + g;
                bh[n][0] = *(unsigned*)&Whi[n0 * AST + k0 + q * 2];
                bh[n][1] = *(unsigned*)&Whi[n0 * AST + k0 + 8 + q * 2];
                bl[n][0] = *(unsigned*)&Wlo[n0 * AST + k0 + q * 2];
                bl[n][1] = *(unsigned*)&Wlo[n0 * AST + k0 + 8 + q * 2];
            }
#pragma unroll
            for (int m = 0; m < 2; m++)
#pragma unroll
                for (int n = 0; n < 8; n++) {
                    mma16816(c[m * 8 + n], ah[m], bh[n]);
                    mma16816(c[m * 8 + n], al[m], bh[n]);
                    mma16816(c[m * 8 + n], ah[m], bl[n]);
                }
        }

#pragma unroll
        for (int n = 0; n < 8; n++) {
            int col = wc + n * 8 + q * 2;
            float b0 = bias_s[col], b1 = bias_s[col + 1];
            float s0 = 0.f, s1 = 0.f, q0 = 0.f, q1 = 0.f;
#pragma unroll
            for (int m = 0; m < 2; m++) {
                int row0 = ti * 128 + wr + m * 16 + g;
                float* cf = c[m * 8 + n];
                float v0 = cf[0] + b0, v1 = cf[1] + b1;
                float v2 = cf[2] + b0, v3 = cf[3] + b1;
                if (row0 < NND) {
                    *(float2*)&Z[(size_t)row0 * DD + col] = make_float2(v0, v1);
                    s0 += v0; s1 += v1; q0 += v0 * v0; q1 += v1 * v1;
                }
                if (row0 + 8 < NND) {
                    *(float2*)&Z[(size_t)(row0 + 8) * DD + col] = make_float2(v2, v3);
                    s0 += v2; s1 += v3; q0 += v2 * v2; q1 += v3 * v3;
                }
            }
#pragma unroll
            for (int o = 4; o < 32; o <<= 1) {
                s0 += __shfl_xor_sync(0xffffffffu, s0, o);
                s1 += __shfl_xor_sync(0xffffffffu, s1, o);
                q0 += __shfl_xor_sync(0xffffffffu, q0, o);
                q1 += __shfl_xor_sync(0xffffffffu, q1, o);
            }
            if (lane < 4) {
                atomicAdd(&colsum[col], s0);
                atomicAdd(&colsum[col + 1], s1);
                atomicAdd(&colsq[col], q0);
                atomicAdd(&colsq[col + 1], q1);
            }
        }
    }

    __syncthreads();
    if (t < DD) {
        atomicAdd(&statsOut[t], colsum[t]);
        atomicAdd(&statsOut[DD + t], colsq[t]);
    }
}

// ---------------- BN-on-the-fly segmented graph pooling ----------------
__global__ void k_pool(float* __restrict__ pg, const float* __restrict__ Z,
                       const float* __restrict__ gam, const float* __restrict__ bet,
                       const float* __restrict__ stats, const int* __restrict__ gids) {
    __shared__ float sc[DD], sh[DD];
    int t = threadIdx.x;
    if (t < DD) {
        const float inv_n = 1.0f / (float)NND;
        float mu = stats[t] * inv_n;
        float var = stats[DD + t] * inv_n - mu * mu;
        float s = __ldg(&gam[t]) * rsqrtf(var + BN_EPS);
        sc[t] = s;
        sh[t] = __ldg(&bet[t]) - mu * s;
    }
    __syncthreads();
    int warp = (blockIdx.x * blockDim.x + t) >> 5;
    int lane = t & 31;
    int r0 = warp * 32;
    if (r0 >= NND) return;
    int r1 = min(r0 + 32, NND);
    int ch = lane * 4;
    float c0 = sc[ch], c1 = sc[ch + 1], c2 = sc[ch + 2], c3 = sc[ch + 3];
    float h0 = sh[ch], h1 = sh[ch + 1], h2 = sh[ch + 2], h3 = sh[ch + 3];
    int cur = __ldg(&gids[r0]);
    float4 acc = make_float4(0.f, 0.f, 0.f, 0.f);
    for (int r = r0; r < r1; r++) {
        int gid = __ldg(&gids[r]);
        if (gid != cur) {
            red_add_v4(&pg[cur * DD + ch], acc);
            acc = make_float4(0.f, 0.f, 0.f, 0.f);
            cur = gid;
        }
        float4 v = ((const float4*)Z)[r * 32 + lane];
        acc.x += fmaxf(v.x * c0 + h0, 0.f);
        acc.y += fmaxf(v.y * c1 + h1, 0.f);
        acc.z += fmaxf(v.z * c2 + h2, 0.f);
        acc.w += fmaxf(v.w * c3 + h3, 0.f);
    }
    red_add_v4(&pg[cur * DD + ch], acc);
}

__global__ void k_gpool(float* __restrict__ pg, const float* __restrict__ h,
                        const int* __restrict__ gids) {
    int warp = (blockIdx.x * blockDim.x + threadIdx.x) >> 5;
    int lane = threadIdx.x & 31;
    int r0 = warp * 32;
    if (r0 >= NND) return;
    int r1 = min(r0 + 32, NND);
    int ch = lane * 4;
    int cur = __ldg(&gids[r0]);
    float4 acc = make_float4(0.f, 0.f, 0.f, 0.f);
    for (int r = r0; r < r1; r++) {
        int gid = __ldg(&gids[r]);
        if (gid != cur) {
            red_add_v4(&pg[cur * DD + ch], acc);
            acc = make_float4(0.f, 0.f, 0.f, 0.f);
            cur = gid;
        }
        float4 v = ((const float4*)h)[r * 32 + lane];
        acc.x += v.x; acc.y += v.y; acc.z += v.z; acc.w += v.w;
    }
    red_add_v4(&pg[cur * DD + ch], acc);
}

__global__ void k_readout(float* __restrict__ out,
                          const float* __restrict__ predW,
                          const float* __restrict__ predb) {
    int g = blockIdx.x;
    int o = threadIdx.x;
    float acc = 0.f;
#pragma unroll
    for (int l = 0; l < NL + 1; l++) {
        const float* pgrow = &g_pg[l * NG * DD + g * DD];
        const float* Wl = &predW[l * DD * OUTD];
        float a = 0.f;
        for (int k = 0; k < DD; k++)
            a += pgrow[k] * __ldg(&Wl[k * OUTD + o]);
        acc += a + __ldg(&predb[l * OUTD + o]);
    }
    out[g * OUTD + o] = acc;
}

// ---------------- launch ----------------
extern "C" void kernel_launch(void* const* d_in, const int* in_sizes, int n_in,
                              void* d_out, int out_size) {
    const float* x     = (const float*)d_in[0];
    const int* esrc    = (const int*)d_in[1];
    const int* edst    = (const int*)d_in[2];
    const int* gids    = (const int*)d_in[3];
    const float* eps   = (const float*)d_in[4];
    const float* W1    = (const float*)d_in[5];
    const float* b1    = (const float*)d_in[6];
    const float* g1    = (const float*)d_in[7];
    const float* be1   = (const float*)d_in[8];
    const float* W2    = (const float*)d_in[9];
    const float* b2    = (const float*)d_in[10];
    const float* g2    = (const float*)d_in[11];
    const float* be2   = (const float*)d_in[12];
    const float* predW = (const float*)d_in[13];
    const float* predb = (const float*)d_in[14];
    float* out = (float*)d_out;

    float *Z, *Z2, *stats, *pg;
    int* deg;
    cudaGetSymbolAddress((void**)&Z, g_Z);
    cudaGetSymbolAddress((void**)&Z2, g_Z2);
    cudaGetSymbolAddress((void**)&stats, g_stats);
    cudaGetSymbolAddress((void**)&pg, g_pg);
    cudaGetSymbolAddress((void**)&deg, g_deg);
    float* s0 = stats;
    float* s1 = stats + 2 * DD;

    const int smem_ma = 4 * DD * AST * (int)sizeof(unsigned short);          // 135168
    const int smem_mm = smem_ma + 65536;                                     // 200704
    static bool attr_set = false;
    if (!attr_set) {
        cudaFuncSetAttribute(k_mmagg, cudaFuncAttributeMaxDynamicSharedMemorySize, smem_ma);
        cudaFuncSetAttribute(k_mm, cudaFuncAttributeMaxDynamicSharedMemorySize, smem_mm);
        attr_set = true;
    }

    const int gridEdge = (NE + 255) / 256;
    const int nWarps = (NND + 31) / 32;
    const int gridSeg = (nWarps * 32 + 255) / 256;

    // CSR build (once; shared by all 4 layers)
    cudaMemsetAsync(deg, 0, sizeof(int) * NND);
    k_hist<<<gridEdge, 256>>>(edst);
    k_scan<<<1, 1024>>>();
    k_scatter<<<gridEdge, 256>>>(esrc, edst);

    // layer-0 graph pooling
    cudaMemsetAsync(pg, 0, sizeof(float) * (NL + 1) * NG * DD);
    k_gpool<<<gridSeg, 256>>>(pg, x, gids);

    for (int l = 0; l < NL; l++) {
        cudaMemsetAsync(s0, 0, sizeof(float) * 2 * DD);
        if (l == 0)
            k_mmagg<<<148, 512, smem_ma>>>(Z, x, W1, b1, nullptr, nullptr, nullptr,
                                           eps, l, s0);
        else
            k_mmagg<<<148, 512, smem_ma>>>(Z, Z2, W1 + l * DD * DD, b1 + l * DD,
                                           g2 + (l - 1) * DD, be2 + (l - 1) * DD, s1,
                                           eps, l, s0);

        cudaMemsetAsync(s1, 0, sizeof(float) * 2 * DD);
        k_mm<<<148, 256, smem_mm>>>(Z2, Z, W2 + l * DD * DD, b2 + l * DD,
                                    g1 + l * DD, be1 + l * DD, s0, s1);

        k_pool<<<gridSeg, 256>>>(pg + (l + 1) * NG * DD, Z2,
                                 g2 + l * DD, be2 + l * DD, s1, gids);
    }

    k_readout<<<NG, OUTD>>>(out, predW, predb);
}

// round 11
// speedup vs baseline: 1.1317x; 1.1317x over previous
#include <cuda_runtime.h>
#include <cuda_bf16.h>

#define NND 100000
#define NE  1600000
#define NG  128
#define DD  128
#define OUTD 64
#define NL  4
#define BN_EPS 1e-5f
#define NT  782                    // ceil(NND/128)
#define AST 132                    // smem row stride in bf16 elems

// ---------------- scratch (device globals; no allocation) ----------------
__device__ float g_P[NND * DD];
__device__ float g_Z[NND * DD];     // GEMM1 output
__device__ float g_Z2[NND * DD];    // GEMM2 output
__device__ float g_stats[2][2 * DD];
__device__ float g_pg[(NL + 1) * NG * DD];
__device__ int   g_deg[NND];
__device__ int   g_off[NND + 1];
__device__ int   g_cur[NND];
__device__ int   g_esrt[NE];

// ---------------- helpers ----------------
__device__ __forceinline__ void red_add_v4(float* addr, float4 v) {
    asm volatile("red.global.add.v4.f32 [%0], {%1, %2, %3, %4};"
                 :: "l"(addr), "f"(v.x), "f"(v.y), "f"(v.z), "f"(v.w) : "memory");
}
__device__ __forceinline__ unsigned cvt2bf(float lo, float hi) {
    unsigned r;
    asm("cvt.rn.bf16x2.f32 %0, %1, %2;" : "=r"(r) : "f"(hi), "f"(lo));
    return r;
}
__device__ __forceinline__ void mma16816(float* c, const unsigned* a, const unsigned* b) {
    asm volatile("mma.sync.aligned.m16n8k16.row.col.f32.bf16.bf16.f32 "
                 "{%0,%1,%2,%3}, {%4,%5,%6,%7}, {%8,%9}, {%0,%1,%2,%3};"
                 : "+f"(c[0]), "+f"(c[1]), "+f"(c[2]), "+f"(c[3])
                 : "r"(a[0]), "r"(a[1]), "r"(a[2]), "r"(a[3]), "r"(b[0]), "r"(b[1]));
}
__device__ __forceinline__ void cpasync16(unsigned saddr, const void* g, int sz) {
    asm volatile("cp.async.cg.shared.global [%0], [%1], 16, %2;"
                 :: "r"(saddr), "l"(g), "r"(sz) : "memory");
}
#define CP_COMMIT() asm volatile("cp.async.commit_group;" ::: "memory")
#define CP_WAIT0()  asm volatile("cp.async.wait_group 0;" ::: "memory")

// ---------------- CSR build ----------------
__global__ void k_hist(const int* __restrict__ dst) {
    int e = blockIdx.x * blockDim.x + threadIdx.x;
    if (e < NE) atomicAdd(&g_deg[__ldg(&dst[e])], 1);
}
__global__ void k_scan() {
    __shared__ int sp[1024];
    int t = threadIdx.x;
    int base = t * 98;
    int s = 0;
    for (int i = 0; i < 98; i++) { int j = base + i; if (j < NND) s += g_deg[j]; }
    sp[t] = s;
    __syncthreads();
    for (int o = 1; o < 1024; o <<= 1) {
        int v = (t >= o) ? sp[t - o] : 0;
        __syncthreads();
        sp[t] += v;
        __syncthreads();
    }
    int run = t ? sp[t - 1] : 0;
    for (int i = 0; i < 98; i++) {
        int j = base + i;
        if (j < NND) { g_off[j] = run; g_cur[j] = run; run += g_deg[j]; }
    }
    if (t == 0) g_off[NND] = NE;
}
__global__ void k_scatter(const int* __restrict__ src, const int* __restrict__ dst) {
    int e = blockIdx.x * blockDim.x + threadIdx.x;
    if (e >= NE) return;
    int pos = atomicAdd(&g_cur[__ldg(&dst[e])], 1);
    g_esrt[pos] = __ldg(&src[e]);
}

// ---- aggregation with fused input BN+relu, deep-unrolled gather (MLP=8):
// h[r] = doBN ? relu(Zs[r]*sc+sh) : Zs[r];  P[d] = (1+eps)h[d] + sum h[src]
__global__ void k_agg(float* __restrict__ P, const float* __restrict__ Zs,
                      const float* __restrict__ eps, int l,
                      const float* __restrict__ gam, const float* __restrict__ bet,
                      const float* __restrict__ stats) {
    __shared__ float sc[DD], sh[DD];
    int t = threadIdx.x;
    const bool doBN = (gam != nullptr);
    if (doBN && t < DD) {
        const float inv_n = 1.0f / (float)NND;
        float mu = stats[t] * inv_n;
        float var = stats[DD + t] * inv_n - mu * mu;
        float s = __ldg(&gam[t]) * rsqrtf(var + BN_EPS);
        sc[t] = s;
        sh[t] = __ldg(&bet[t]) - mu * s;
    }
    __syncthreads();
    int gw = (blockIdx.x * blockDim.x + t) >> 5;
    int lane = t & 31;
    if (gw >= NND) return;
    int ch = lane * 4;
    float c0 = 1.f, c1 = 1.f, c2 = 1.f, c3 = 1.f, h0 = 0.f, h1 = 0.f, h2 = 0.f, h3 = 0.f;
    if (doBN) {
        c0 = sc[ch]; c1 = sc[ch + 1]; c2 = sc[ch + 2]; c3 = sc[ch + 3];
        h0 = sh[ch]; h1 = sh[ch + 1]; h2 = sh[ch + 2]; h3 = sh[ch + 3];
    }
#define BN4(v) do { if (doBN) { \
        (v).x = fmaxf((v).x * c0 + h0, 0.f); (v).y = fmaxf((v).y * c1 + h1, 0.f); \
        (v).z = fmaxf((v).z * c2 + h2, 0.f); (v).w = fmaxf((v).w * c3 + h3, 0.f); } } while (0)

    int e0 = __ldg(&g_off[gw]), e1 = __ldg(&g_off[gw + 1]);
    float e = 1.0f + __ldg(&eps[l]);

    float4 v = __ldg((const float4*)Zs + gw * 32 + lane);
    BN4(v);
    float4 acc = make_float4(v.x * e, v.y * e, v.z * e, v.w * e);

    int i = e0;
    // unroll-8: 8 independent row gathers in flight per warp
    for (; i + 7 < e1; i += 8) {
        int xx[8];
#pragma unroll
        for (int j = 0; j < 8; j++) xx[j] = __ldg(&g_esrt[i + j]);
        float4 aa[8];
#pragma unroll
        for (int j = 0; j < 8; j++)
            aa[j] = __ldg((const float4*)Zs + (size_t)xx[j] * 32 + lane);
#pragma unroll
        for (int j = 0; j < 8; j++) {
            BN4(aa[j]);
            acc.x += aa[j].x; acc.y += aa[j].y; acc.z += aa[j].z; acc.w += aa[j].w;
        }
    }
    // unroll-2 remainder
    for (; i + 1 < e1; i += 2) {
        int x0 = __ldg(&g_esrt[i]), x1 = __ldg(&g_esrt[i + 1]);
        float4 a0 = __ldg((const float4*)Zs + (size_t)x0 * 32 + lane);
        float4 a1 = __ldg((const float4*)Zs + (size_t)x1 * 32 + lane);
        BN4(a0); BN4(a1);
        acc.x += a0.x + a1.x; acc.y += a0.y + a1.y;
        acc.z += a0.z + a1.z; acc.w += a0.w + a1.w;
    }
    if (i < e1) {
        int x0 = __ldg(&g_esrt[i]);
        float4 a0 = __ldg((const float4*)Zs + (size_t)x0 * 32 + lane);
        BN4(a0);
        acc.x += a0.x; acc.y += a0.y; acc.z += a0.z; acc.w += a0.w;
    }
#undef BN4
    ((float4*)P)[gw * 32 + lane] = acc;
}

// ---------------- HMMA bf16x3 GEMM, cp.async-staged, fused stats & input-BN ----------
__global__ void __launch_bounds__(256, 1)
k_mm(float* __restrict__ Z, const float* __restrict__ A,
     const float* __restrict__ W, const float* __restrict__ bias,
     const float* __restrict__ gam, const float* __restrict__ bet,
     const float* __restrict__ statsIn, float* __restrict__ statsOut) {
    extern __shared__ unsigned short sm[];
    unsigned short* Whi = sm;
    unsigned short* Wlo = sm + DD * AST;
    unsigned short* Ahi = sm + 2 * DD * AST;
    unsigned short* Alo = sm + 3 * DD * AST;
    float* Sg = (float*)(sm + 4 * DD * AST);
    __shared__ float colsum[DD], colsq[DD], bias_s[DD], scA[DD], shA[DD];

    const int t = threadIdx.x;
    const int w = t >> 5, lane = t & 31;
    const int g = lane >> 2, q = lane & 3;
    const int wr = (w & 3) * 32;
    const int wc = (w >> 2) * 64;
    const bool doBN = (gam != nullptr);
    const unsigned sgBase = (unsigned)__cvta_generic_to_shared(Sg);

    {
        int ti = blockIdx.x;
#pragma unroll
        for (int i = 0; i < 16; i++) {
            int fi = t + i * 256;
            int row = fi >> 5, kq = fi & 31;
            int grow = ti * 128 + row;
            bool valid = grow < NND;
            const float4* gp = (const float4*)A + ((size_t)(valid ? grow : 0) * 32 + kq);
            cpasync16(sgBase + fi * 16, gp, valid ? 16 : 0);
        }
        CP_COMMIT();
    }

    for (int e = t; e < DD * DD; e += 256) {
        int k = e >> 7, n = e & 127;
        float x = __ldg(&W[k * DD + n]);
        unsigned xu = __float_as_uint(x);
        Whi[n * AST + k] = (unsigned short)(xu >> 16);
        unsigned lp = cvt2bf(x - __uint_as_float(xu & 0xffff0000u), 0.f);
        Wlo[n * AST + k] = (unsigned short)(lp & 0xffff);
    }
    if (t < DD) {
        colsum[t] = 0.f; colsq[t] = 0.f; bias_s[t] = __ldg(&bias[t]);
        if (doBN) {
            const float inv_n = 1.0f / (float)NND;
            float mu = statsIn[t] * inv_n;
            float var = statsIn[DD + t] * inv_n - mu * mu;
            float s = __ldg(&gam[t]) * rsqrtf(var + BN_EPS);
            scA[t] = s;
            shA[t] = __ldg(&bet[t]) - mu * s;
        }
    }

    for (int ti = blockIdx.x; ti < NT; ti += gridDim.x) {
        CP_WAIT0();
        __syncthreads();

#pragma unroll
        for (int i = 0; i < 16; i++) {
            int fi = t + i * 256;
            int row = fi >> 5, kq = fi & 31;
            float4 v = ((const float4*)Sg)[fi];
            if (doBN) {
                int ch = kq * 4;
                v.x = fmaxf(v.x * scA[ch] + shA[ch], 0.f);
                v.y = fmaxf(v.y * scA[ch + 1] + shA[ch + 1], 0.f);
                v.z = fmaxf(v.z * scA[ch + 2] + shA[ch + 2], 0.f);
                v.w = fmaxf(v.w * scA[ch + 3] + shA[ch + 3], 0.f);
            }
            unsigned hx = __byte_perm(__float_as_uint(v.x), __float_as_uint(v.y), 0x7632);
            unsigned hy = __byte_perm(__float_as_uint(v.z), __float_as_uint(v.w), 0x7632);
            unsigned lx = cvt2bf(v.x - __uint_as_float(__float_as_uint(v.x) & 0xffff0000u),
                                 v.y - __uint_as_float(__float_as_uint(v.y) & 0xffff0000u));
            unsigned ly = cvt2bf(v.z - __uint_as_float(__float_as_uint(v.z) & 0xffff0000u),
                                 v.w - __uint_as_float(__float_as_uint(v.w) & 0xffff0000u));
            *(uint2*)&Ahi[row * AST + kq * 4] = make_uint2(hx, hy);
            *(uint2*)&Alo[row * AST + kq * 4] = make_uint2(lx, ly);
        }
        __syncthreads();

        int tn = ti + gridDim.x;
        if (tn < NT) {
#pragma unroll
            for (int i = 0; i < 16; i++) {
                int fi = t + i * 256;
                int row = fi >> 5, kq = fi & 31;
                int grow = tn * 128 + row;
                bool valid = grow < NND;
                const float4* gp = (const float4*)A + ((size_t)(valid ? grow : 0) * 32 + kq);
                cpasync16(sgBase + fi * 16, gp, valid ? 16 : 0);
            }
            CP_COMMIT();
        }

        float c[16][4];
#pragma unroll
        for (int i = 0; i < 16; i++)
#pragma unroll
            for (int j = 0; j < 4; j++) c[i][j] = 0.f;

#pragma unroll
        for (int ks = 0; ks < 8; ks++) {
            int k0 = ks * 16;
            unsigned ah[2][4], al[2][4];
#pragma unroll
            for (int m = 0; m < 2; m++) {
                int r0 = wr + m * 16;
                ah[m][0] = *(unsigned*)&Ahi[(r0 + g) * AST + k0 + q * 2];
                ah[m][1] = *(unsigned*)&Ahi[(r0 + g + 8) * AST + k0 + q * 2];
                ah[m][2] = *(unsigned*)&Ahi[(r0 + g) * AST + k0 + 8 + q * 2];
                ah[m][3] = *(unsigned*)&Ahi[(r0 + g + 8) * AST + k0 + 8 + q * 2];
                al[m][0] = *(unsigned*)&Alo[(r0 + g) * AST + k0 + q * 2];
                al[m][1] = *(unsigned*)&Alo[(r0 + g + 8) * AST + k0 + q * 2];
                al[m][2] = *(unsigned*)&Alo[(r0 + g) * AST + k0 + 8 + q * 2];
                al[m][3] = *(unsigned*)&Alo[(r0 + g + 8) * AST + k0 + 8 + q * 2];
            }
            unsigned bh[8][2], bl[8][2];
#pragma unroll
            for (int n = 0; n < 8; n++) {
                int n0 = wc + n * 8 + g;
                bh[n][0] = *(unsigned*)&Whi[n0 * AST + k0 + q * 2];
                bh[n][1] = *(unsigned*)&Whi[n0 * AST + k0 + 8 + q * 2];
                bl[n][0] = *(unsigned*)&Wlo[n0 * AST + k0 + q * 2];
                bl[n][1] = *(unsigned*)&Wlo[n0 * AST + k0 + 8 + q * 2];
            }
#pragma unroll
            for (int m = 0; m < 2; m++)
#pragma unroll
                for (int n = 0; n < 8; n++) {
                    mma16816(c[m * 8 + n], ah[m], bh[n]);
                    mma16816(c[m * 8 + n], al[m], bh[n]);
                    mma16816(c[m * 8 + n], ah[m], bl[n]);
                }
        }

#pragma unroll
        for (int n = 0; n < 8; n++) {
            int col = wc + n * 8 + q * 2;
            float b0 = bias_s[col], b1 = bias_s[col + 1];
            float s0 = 0.f, s1 = 0.f, q0 = 0.f, q1 = 0.f;
#pragma unroll
            for (int m = 0; m < 2; m++) {
                int row0 = ti * 128 + wr + m * 16 + g;
                float* cf = c[m * 8 + n];
                float v0 = cf[0] + b0, v1 = cf[1] + b1;
                float v2 = cf[2] + b0, v3 = cf[3] + b1;
                if (row0 < NND) {
                    *(float2*)&Z[(size_t)row0 * DD + col] = make_float2(v0, v1);
                    s0 += v0; s1 += v1; q0 += v0 * v0; q1 += v1 * v1;
                }
                if (row0 + 8 < NND) {
                    *(float2*)&Z[(size_t)(row0 + 8) * DD + col] = make_float2(v2, v3);
                    s0 += v2; s1 += v3; q0 += v2 * v2; q1 += v3 * v3;
                }
            }
#pragma unroll
            for (int o = 4; o < 32; o <<= 1) {
                s0 += __shfl_xor_sync(0xffffffffu, s0, o);
                s1 += __shfl_xor_sync(0xffffffffu, s1, o);
                q0 += __shfl_xor_sync(0xffffffffu, q0, o);
                q1 += __shfl_xor_sync(0xffffffffu, q1, o);
            }
            if (lane < 4) {
                atomicAdd(&colsum[col], s0);
                atomicAdd(&colsum[col + 1], s1);
                atomicAdd(&colsq[col], q0);
                atomicAdd(&colsq[col + 1], q1);
            }
        }
    }

    __syncthreads();
    if (t < DD) {
        atomicAdd(&statsOut[t], colsum[t]);
        atomicAdd(&statsOut[DD + t], colsq[t]);
    }
}

// ---------------- BN-on-the-fly segmented graph pooling (no H write) ----------------
__global__ void k_pool(float* __restrict__ pg, const float* __restrict__ Z,
                       const float* __restrict__ gam, const float* __restrict__ bet,
                       const float* __restrict__ stats, const int* __restrict__ gids) {
    __shared__ float sc[DD], sh[DD];
    int t = threadIdx.x;
    if (t < DD) {
        const float inv_n = 1.0f / (float)NND;
        float mu = stats[t] * inv_n;
        float var = stats[DD + t] * inv_n - mu * mu;
        float s = __ldg(&gam[t]) * rsqrtf(var + BN_EPS);
        sc[t] = s;
        sh[t] = __ldg(&bet[t]) - mu * s;
    }
    __syncthreads();
    int warp = (blockIdx.x * blockDim.x + t) >> 5;
    int lane = t & 31;
    int r0 = warp * 32;
    if (r0 >= NND) return;
    int r1 = min(r0 + 32, NND);
    int ch = lane * 4;
    float c0 = sc[ch], c1 = sc[ch + 1], c2 = sc[ch + 2], c3 = sc[ch + 3];
    float h0 = sh[ch], h1 = sh[ch + 1], h2 = sh[ch + 2], h3 = sh[ch + 3];
    int cur = __ldg(&gids[r0]);
    float4 acc = make_float4(0.f, 0.f, 0.f, 0.f);
    for (int r = r0; r < r1; r++) {
        int gid = __ldg(&gids[r]);
        if (gid != cur) {
            red_add_v4(&pg[cur * DD + ch], acc);
            acc = make_float4(0.f, 0.f, 0.f, 0.f);
            cur = gid;
        }
        float4 v = ((const float4*)Z)[r * 32 + lane];
        acc.x += fmaxf(v.x * c0 + h0, 0.f);
        acc.y += fmaxf(v.y * c1 + h1, 0.f);
        acc.z += fmaxf(v.z * c2 + h2, 0.f);
        acc.w += fmaxf(v.w * c3 + h3, 0.f);
    }
    red_add_v4(&pg[cur * DD + ch], acc);
}

// segmented pooling for layer-0 (h = x, no BN)
__global__ void k_gpool(float* __restrict__ pg, const float* __restrict__ h,
                        const int* __restrict__ gids) {
    int warp = (blockIdx.x * blockDim.x + threadIdx.x) >> 5;
    int lane = threadIdx.x & 31;
    int r0 = warp * 32;
    if (r0 >= NND) return;
    int r1 = min(r0 + 32, NND);
    int ch = lane * 4;
    int cur = __ldg(&gids[r0]);
    float4 acc = make_float4(0.f, 0.f, 0.f, 0.f);
    for (int r = r0; r < r1; r++) {
        int gid = __ldg(&gids[r]);
        if (gid != cur) {
            red_add_v4(&pg[cur * DD + ch], acc);
            acc = make_float4(0.f, 0.f, 0.f, 0.f);
            cur = gid;
        }
        float4 v = ((const float4*)h)[r * 32 + lane];
        acc.x += v.x; acc.y += v.y; acc.z += v.z; acc.w += v.w;
    }
    red_add_v4(&pg[cur * DD + ch], acc);
}

__global__ void k_readout(float* __restrict__ out,
                          const float* __restrict__ predW,
                          const float* __restrict__ predb) {
    int g = blockIdx.x;
    int o = threadIdx.x;
    float acc = 0.f;
#pragma unroll
    for (int l = 0; l < NL + 1; l++) {
        const float* pgrow = &g_pg[l * NG * DD + g * DD];
        const float* Wl = &predW[l * DD * OUTD];
        float a = 0.f;
        for (int k = 0; k < DD; k++)
            a += pgrow[k] * __ldg(&Wl[k * OUTD + o]);
        acc += a + __ldg(&predb[l * OUTD + o]);
    }
    out[g * OUTD + o] = acc;
}

// ---------------- launch ----------------
extern "C" void kernel_launch(void* const* d_in, const int* in_sizes, int n_in,
                              void* d_out, int out_size) {
    const float* x     = (const float*)d_in[0];
    const int* esrc    = (const int*)d_in[1];
    const int* edst    = (const int*)d_in[2];
    const int* gids    = (const int*)d_in[3];
    const float* eps   = (const float*)d_in[4];
    const float* W1    = (const float*)d_in[5];
    const float* b1    = (const float*)d_in[6];
    const float* g1    = (const float*)d_in[7];
    const float* be1   = (const float*)d_in[8];
    const float* W2    = (const float*)d_in[9];
    const float* b2    = (const float*)d_in[10];
    const float* g2    = (const float*)d_in[11];
    const float* be2   = (const float*)d_in[12];
    const float* predW = (const float*)d_in[13];
    const float* predb = (const float*)d_in[14];
    float* out = (float*)d_out;

    float *P, *Z, *Z2, *stats, *pg;
    int* deg;
    cudaGetSymbolAddress((void**)&P, g_P);
    cudaGetSymbolAddress((void**)&Z, g_Z);
    cudaGetSymbolAddress((void**)&Z2, g_Z2);
    cudaGetSymbolAddress((void**)&stats, g_stats);
    cudaGetSymbolAddress((void**)&pg, g_pg);
    cudaGetSymbolAddress((void**)&deg, g_deg);
    float* s0 = stats;
    float* s1 = stats + 2 * DD;

    const int smem_mm = 4 * DD * AST * (int)sizeof(unsigned short) + 65536;  // 200704
    static bool attr_set = false;
    if (!attr_set) {
        cudaFuncSetAttribute(k_mm, cudaFuncAttributeMaxDynamicSharedMemorySize, smem_mm);
        attr_set = true;
    }

    const int gridEdge = (NE + 255) / 256;
    const int nWarps = (NND + 31) / 32;
    const int gridSeg = (nWarps * 32 + 255) / 256;

    // CSR build (once; shared by all 4 layers)
    cudaMemsetAsync(deg, 0, sizeof(int) * NND);
    k_hist<<<gridEdge, 256>>>(edst);
    k_scan<<<1, 1024>>>();
    k_scatter<<<gridEdge, 256>>>(esrc, edst);

    // layer-0 graph pooling
    cudaMemsetAsync(pg, 0, sizeof(float) * (NL + 1) * NG * DD);
    k_gpool<<<gridSeg, 256>>>(pg, x, gids);

    for (int l = 0; l < NL; l++) {
        if (l == 0)
            k_agg<<<(NND + 7) / 8, 256>>>(P, x, eps, l, nullptr, nullptr, nullptr);
        else
            k_agg<<<(NND + 7) / 8, 256>>>(P, Z2, eps, l,
                                          g2 + (l - 1) * DD, be2 + (l - 1) * DD, s1);

        cudaMemsetAsync(s0, 0, sizeof(float) * 2 * DD);
        k_mm<<<148, 256, smem_mm>>>(Z, P, W1 + l * DD * DD, b1 + l * DD,
                                    nullptr, nullptr, nullptr, s0);

        cudaMemsetAsync(s1, 0, sizeof(float) * 2 * DD);
        k_mm<<<148, 256, smem_mm>>>(Z2, Z, W2 + l * DD * DD, b2 + l * DD,
                                    g1 + l * DD, be1 + l * DD, s0, s1);

        k_pool<<<gridSeg, 256>>>(pg + (l + 1) * NG * DD, Z2,
                                 g2 + l * DD, be2 + l * DD, s1, gids);
    }

    k_readout<<<NG, OUTD>>>(out, predW, predb);
}

// round 12
// speedup vs baseline: 1.2260x; 1.0833x over previous
#include <cuda_runtime.h>
#include <cuda_bf16.h>

#define NND 100000
#define NE  1600000
#define NG  128
#define DD  128
#define OUTD 64
#define NL  4
#define BN_EPS 1e-5f
#define NT  782                    // ceil(NND/128)
#define AST 132                    // smem row stride in bf16 elems

// ---------------- scratch (device globals; no allocation) ----------------
__device__ float g_P[NND * DD];
__device__ float g_Z[NND * DD];     // GEMM1 output
__device__ float g_Z2[NND * DD];    // GEMM2 output
__device__ float g_stats[2][2 * DD];
__device__ float g_pg[(NL + 1) * NG * DD];
__device__ int   g_deg[NND];
__device__ int   g_off[NND + 1];
__device__ int   g_cur[NND];
__device__ int   g_esrt[NE];

// ---------------- helpers ----------------
__device__ __forceinline__ void red_add_v4(float* addr, float4 v) {
    asm volatile("red.global.add.v4.f32 [%0], {%1, %2, %3, %4};"
                 :: "l"(addr), "f"(v.x), "f"(v.y), "f"(v.z), "f"(v.w) : "memory");
}
__device__ __forceinline__ unsigned cvt2bf(float lo, float hi) {
    unsigned r;
    asm("cvt.rn.bf16x2.f32 %0, %1, %2;" : "=r"(r) : "f"(hi), "f"(lo));
    return r;
}
__device__ __forceinline__ void mma16816(float* c, const unsigned* a, const unsigned* b) {
    asm volatile("mma.sync.aligned.m16n8k16.row.col.f32.bf16.bf16.f32 "
                 "{%0,%1,%2,%3}, {%4,%5,%6,%7}, {%8,%9}, {%0,%1,%2,%3};"
                 : "+f"(c[0]), "+f"(c[1]), "+f"(c[2]), "+f"(c[3])
                 : "r"(a[0]), "r"(a[1]), "r"(a[2]), "r"(a[3]), "r"(b[0]), "r"(b[1]));
}
__device__ __forceinline__ void cpasync16(unsigned saddr, const void* g, int sz) {
    asm volatile("cp.async.cg.shared.global [%0], [%1], 16, %2;"
                 :: "r"(saddr), "l"(g), "r"(sz) : "memory");
}
#define CP_COMMIT() asm volatile("cp.async.commit_group;" ::: "memory")
#define CP_WAIT0()  asm volatile("cp.async.wait_group 0;" ::: "memory")

// ---------------- CSR build ----------------
__global__ void k_hist(const int* __restrict__ dst) {
    int e = blockIdx.x * blockDim.x + threadIdx.x;
    if (e < NE) atomicAdd(&g_deg[__ldg(&dst[e])], 1);
}
__global__ void k_scan() {
    __shared__ int sp[1024];
    int t = threadIdx.x;
    int base = t * 98;
    int s = 0;
    for (int i = 0; i < 98; i++) { int j = base + i; if (j < NND) s += g_deg[j]; }
    sp[t] = s;
    __syncthreads();
    for (int o = 1; o < 1024; o <<= 1) {
        int v = (t >= o) ? sp[t - o] : 0;
        __syncthreads();
        sp[t] += v;
        __syncthreads();
    }
    int run = t ? sp[t - 1] : 0;
    for (int i = 0; i < 98; i++) {
        int j = base + i;
        if (j < NND) { g_off[j] = run; g_cur[j] = run; run += g_deg[j]; }
    }
    if (t == 0) g_off[NND] = NE;
}
__global__ void k_scatter(const int* __restrict__ src, const int* __restrict__ dst) {
    int e = blockIdx.x * blockDim.x + threadIdx.x;
    if (e >= NE) return;
    int pos = atomicAdd(&g_cur[__ldg(&dst[e])], 1);
    g_esrt[pos] = __ldg(&src[e]);
}

// ---- aggregation with fused input BN+relu (unroll-2, proven best):
// h[r] = doBN ? relu(Zs[r]*sc+sh) : Zs[r];  P[d] = (1+eps)h[d] + sum h[src]
// P written with streaming stores so the write stream doesn't evict Zs from L2.
__global__ void k_agg(float* __restrict__ P, const float* __restrict__ Zs,
                      const float* __restrict__ eps, int l,
                      const float* __restrict__ gam, const float* __restrict__ bet,
                      const float* __restrict__ stats) {
    __shared__ float sc[DD], sh[DD];
    int t = threadIdx.x;
    const bool doBN = (gam != nullptr);
    if (doBN && t < DD) {
        const float inv_n = 1.0f / (float)NND;
        float mu = stats[t] * inv_n;
        float var = stats[DD + t] * inv_n - mu * mu;
        float s = __ldg(&gam[t]) * rsqrtf(var + BN_EPS);
        sc[t] = s;
        sh[t] = __ldg(&bet[t]) - mu * s;
    }
    __syncthreads();
    int gw = (blockIdx.x * blockDim.x + t) >> 5;
    int lane = t & 31;
    if (gw >= NND) return;
    int ch = lane * 4;
    float c0 = 1.f, c1 = 1.f, c2 = 1.f, c3 = 1.f, h0 = 0.f, h1 = 0.f, h2 = 0.f, h3 = 0.f;
    if (doBN) {
        c0 = sc[ch]; c1 = sc[ch + 1]; c2 = sc[ch + 2]; c3 = sc[ch + 3];
        h0 = sh[ch]; h1 = sh[ch + 1]; h2 = sh[ch + 2]; h3 = sh[ch + 3];
    }
#define BN4(v) do { if (doBN) { \
        (v).x = fmaxf((v).x * c0 + h0, 0.f); (v).y = fmaxf((v).y * c1 + h1, 0.f); \
        (v).z = fmaxf((v).z * c2 + h2, 0.f); (v).w = fmaxf((v).w * c3 + h3, 0.f); } } while (0)

    int e0 = __ldg(&g_off[gw]), e1 = __ldg(&g_off[gw + 1]);
    float e = 1.0f + __ldg(&eps[l]);

    float4 v = __ldg((const float4*)Zs + gw * 32 + lane);
    BN4(v);
    float4 acc = make_float4(v.x * e, v.y * e, v.z * e, v.w * e);
    int i = e0;
    for (; i + 1 < e1; i += 2) {
        int x0 = __ldg(&g_esrt[i]), x1 = __ldg(&g_esrt[i + 1]);
        float4 a0 = __ldg((const float4*)Zs + (size_t)x0 * 32 + lane);
        float4 a1 = __ldg((const float4*)Zs + (size_t)x1 * 32 + lane);
        BN4(a0); BN4(a1);
        acc.x += a0.x + a1.x; acc.y += a0.y + a1.y;
        acc.z += a0.z + a1.z; acc.w += a0.w + a1.w;
    }
    if (i < e1) {
        int x0 = __ldg(&g_esrt[i]);
        float4 a0 = __ldg((const float4*)Zs + (size_t)x0 * 32 + lane);
        BN4(a0);
        acc.x += a0.x; acc.y += a0.y; acc.z += a0.z; acc.w += a0.w;
    }
#undef BN4
    __stcs((float4*)P + gw * 32 + lane, acc);   // streaming: don't pollute L2
}

// ---------------- HMMA bf16x3 GEMM, cp.async-staged, fused stats & input-BN ----------
__global__ void __launch_bounds__(256, 1)
k_mm(float* __restrict__ Z, const float* __restrict__ A,
     const float* __restrict__ W, const float* __restrict__ bias,
     const float* __restrict__ gam, const float* __restrict__ bet,
     const float* __restrict__ statsIn, float* __restrict__ statsOut) {
    extern __shared__ unsigned short sm[];
    unsigned short* Whi = sm;
    unsigned short* Wlo = sm + DD * AST;
    unsigned short* Ahi = sm + 2 * DD * AST;
    unsigned short* Alo = sm + 3 * DD * AST;
    float* Sg = (float*)(sm + 4 * DD * AST);
    __shared__ float colsum[DD], colsq[DD], bias_s[DD], scA[DD], shA[DD];

    const int t = threadIdx.x;
    const int w = t >> 5, lane = t & 31;
    const int g = lane >> 2, q = lane & 3;
    const int wr = (w & 3) * 32;
    const int wc = (w >> 2) * 64;
    const bool doBN = (gam != nullptr);
    const unsigned sgBase = (unsigned)__cvta_generic_to_shared(Sg);

    {
        int ti = blockIdx.x;
#pragma unroll
        for (int i = 0; i < 16; i++) {
            int fi = t + i * 256;
            int row = fi >> 5, kq = fi & 31;
            int grow = ti * 128 + row;
            bool valid = grow < NND;
            const float4* gp = (const float4*)A + ((size_t)(valid ? grow : 0) * 32 + kq);
            cpasync16(sgBase + fi * 16, gp, valid ? 16 : 0);
        }
        CP_COMMIT();
    }

    for (int e = t; e < DD * DD; e += 256) {
        int k = e >> 7, n = e & 127;
        float x = __ldg(&W[k * DD + n]);
        unsigned xu = __float_as_uint(x);
        Whi[n * AST + k] = (unsigned short)(xu >> 16);
        unsigned lp = cvt2bf(x - __uint_as_float(xu & 0xffff0000u), 0.f);
        Wlo[n * AST + k] = (unsigned short)(lp & 0xffff);
    }
    if (t < DD) {
        colsum[t] = 0.f; colsq[t] = 0.f; bias_s[t] = __ldg(&bias[t]);
        if (doBN) {
            const float inv_n = 1.0f / (float)NND;
            float mu = statsIn[t] * inv_n;
            float var = statsIn[DD + t] * inv_n - mu * mu;
            float s = __ldg(&gam[t]) * rsqrtf(var + BN_EPS);
            scA[t] = s;
            shA[t] = __ldg(&bet[t]) - mu * s;
        }
    }

    for (int ti = blockIdx.x; ti < NT; ti += gridDim.x) {
        CP_WAIT0();
        __syncthreads();

#pragma unroll
        for (int i = 0; i < 16; i++) {
            int fi = t + i * 256;
            int row = fi >> 5, kq = fi & 31;
            float4 v = ((const float4*)Sg)[fi];
            if (doBN) {
                int ch = kq * 4;
                v.x = fmaxf(v.x * scA[ch] + shA[ch], 0.f);
                v.y = fmaxf(v.y * scA[ch + 1] + shA[ch + 1], 0.f);
                v.z = fmaxf(v.z * scA[ch + 2] + shA[ch + 2], 0.f);
                v.w = fmaxf(v.w * scA[ch + 3] + shA[ch + 3], 0.f);
            }
            unsigned hx = __byte_perm(__float_as_uint(v.x), __float_as_uint(v.y), 0x7632);
            unsigned hy = __byte_perm(__float_as_uint(v.z), __float_as_uint(v.w), 0x7632);
            unsigned lx = cvt2bf(v.x - __uint_as_float(__float_as_uint(v.x) & 0xffff0000u),
                                 v.y - __uint_as_float(__float_as_uint(v.y) & 0xffff0000u));
            unsigned ly = cvt2bf(v.z - __uint_as_float(__float_as_uint(v.z) & 0xffff0000u),
                                 v.w - __uint_as_float(__float_as_uint(v.w) & 0xffff0000u));
            *(uint2*)&Ahi[row * AST + kq * 4] = make_uint2(hx, hy);
            *(uint2*)&Alo[row * AST + kq * 4] = make_uint2(lx, ly);
        }
        __syncthreads();

        int tn = ti + gridDim.x;
        if (tn < NT) {
#pragma unroll
            for (int i = 0; i < 16; i++) {
                int fi = t + i * 256;
                int row = fi >> 5, kq = fi & 31;
                int grow = tn * 128 + row;
                bool valid = grow < NND;
                const float4* gp = (const float4*)A + ((size_t)(valid ? grow : 0) * 32 + kq);
                cpasync16(sgBase + fi * 16, gp, valid ? 16 : 0);
            }
            CP_COMMIT();
        }

        float c[16][4];
#pragma unroll
        for (int i = 0; i < 16; i++)
#pragma unroll
            for (int j = 0; j < 4; j++) c[i][j] = 0.f;

#pragma unroll
        for (int ks = 0; ks < 8; ks++) {
            int k0 = ks * 16;
            unsigned ah[2][4], al[2][4];
#pragma unroll
            for (int m = 0; m < 2; m++) {
                int r0 = wr + m * 16;
                ah[m][0] = *(unsigned*)&Ahi[(r0 + g) * AST + k0 + q * 2];
                ah[m][1] = *(unsigned*)&Ahi[(r0 + g + 8) * AST + k0 + q * 2];
                ah[m][2] = *(unsigned*)&Ahi[(r0 + g) * AST + k0 + 8 + q * 2];
                ah[m][3] = *(unsigned*)&Ahi[(r0 + g + 8) * AST + k0 + 8 + q * 2];
                al[m][0] = *(unsigned*)&Alo[(r0 + g) * AST + k0 + q * 2];
                al[m][1] = *(unsigned*)&Alo[(r0 + g + 8) * AST + k0 + q * 2];
                al[m][2] = *(unsigned*)&Alo[(r0 + g) * AST + k0 + 8 + q * 2];
                al[m][3] = *(unsigned*)&Alo[(r0 + g + 8) * AST + k0 + 8 + q * 2];
            }
            unsigned bh[8][2], bl[8][2];
#pragma unroll
            for (int n = 0; n < 8; n++) {
                int n0 = wc + n * 8 + g;
                bh[n][0] = *(unsigned*)&Whi[n0 * AST + k0 + q * 2];
                bh[n][1] = *(unsigned*)&Whi[n0 * AST + k0 + 8 + q * 2];
                bl[n][0] = *(unsigned*)&Wlo[n0 * AST + k0 + q * 2];
                bl[n][1] = *(unsigned*)&Wlo[n0 * AST + k0 + 8 + q * 2];
            }
#pragma unroll
            for (int m = 0; m < 2; m++)
#pragma unroll
                for (int n = 0; n < 8; n++) {
                    mma16816(c[m * 8 + n], ah[m], bh[n]);
                    mma16816(c[m * 8 + n], al[m], bh[n]);
                    mma16816(c[m * 8 + n], ah[m], bl[n]);
                }
        }

#pragma unroll
        for (int n = 0; n < 8; n++) {
            int col = wc + n * 8 + q * 2;
            float b0 = bias_s[col], b1 = bias_s[col + 1];
            float s0 = 0.f, s1 = 0.f, q0 = 0.f, q1 = 0.f;
#pragma unroll
            for (int m = 0; m < 2; m++) {
                int row0 = ti * 128 + wr + m * 16 + g;
                float* cf = c[m * 8 + n];
                float v0 = cf[0] + b0, v1 = cf[1] + b1;
                float v2 = cf[2] + b0, v3 = cf[3] + b1;
                if (row0 < NND) {
                    *(float2*)&Z[(size_t)row0 * DD + col] = make_float2(v0, v1);
                    s0 += v0; s1 += v1; q0 += v0 * v0; q1 += v1 * v1;
                }
                if (row0 + 8 < NND) {
                    *(float2*)&Z[(size_t)(row0 + 8) * DD + col] = make_float2(v2, v3);
                    s0 += v2; s1 += v3; q0 += v2 * v2; q1 += v3 * v3;
                }
            }
#pragma unroll
            for (int o = 4; o < 32; o <<= 1) {
                s0 += __shfl_xor_sync(0xffffffffu, s0, o);
                s1 += __shfl_xor_sync(0xffffffffu, s1, o);
                q0 += __shfl_xor_sync(0xffffffffu, q0, o);
                q1 += __shfl_xor_sync(0xffffffffu, q1, o);
            }
            if (lane < 4) {
                atomicAdd(&colsum[col], s0);
                atomicAdd(&colsum[col + 1], s1);
                atomicAdd(&colsq[col], q0);
                atomicAdd(&colsq[col + 1], q1);
            }
        }
    }

    __syncthreads();
    if (t < DD) {
        atomicAdd(&statsOut[t], colsum[t]);
        atomicAdd(&statsOut[DD + t], colsq[t]);
    }
}

// ---------------- BN-on-the-fly segmented graph pooling (no H write) ----------------
__global__ void k_pool(float* __restrict__ pg, const float* __restrict__ Z,
                       const float* __restrict__ gam, const float* __restrict__ bet,
                       const float* __restrict__ stats, const int* __restrict__ gids) {
    __shared__ float sc[DD], sh[DD];
    int t = threadIdx.x;
    if (t < DD) {
        const float inv_n = 1.0f / (float)NND;
        float mu = stats[t] * inv_n;
        float var = stats[DD + t] * inv_n - mu * mu;
        float s = __ldg(&gam[t]) * rsqrtf(var + BN_EPS);
        sc[t] = s;
        sh[t] = __ldg(&bet[t]) - mu * s;
    }
    __syncthreads();
    int warp = (blockIdx.x * blockDim.x + t) >> 5;
    int lane = t & 31;
    int r0 = warp * 32;
    if (r0 >= NND) return;
    int r1 = min(r0 + 32, NND);
    int ch = lane * 4;
    float c0 = sc[ch], c1 = sc[ch + 1], c2 = sc[ch + 2], c3 = sc[ch + 3];
    float h0 = sh[ch], h1 = sh[ch + 1], h2 = sh[ch + 2], h3 = sh[ch + 3];
    int cur = __ldg(&gids[r0]);
    float4 acc = make_float4(0.f, 0.f, 0.f, 0.f);
    for (int r = r0; r < r1; r++) {
        int gid = __ldg(&gids[r]);
        if (gid != cur) {
            red_add_v4(&pg[cur * DD + ch], acc);
            acc = make_float4(0.f, 0.f, 0.f, 0.f);
            cur = gid;
        }
        float4 v = ((const float4*)Z)[r * 32 + lane];
        acc.x += fmaxf(v.x * c0 + h0, 0.f);
        acc.y += fmaxf(v.y * c1 + h1, 0.f);
        acc.z += fmaxf(v.z * c2 + h2, 0.f);
        acc.w += fmaxf(v.w * c3 + h3, 0.f);
    }
    red_add_v4(&pg[cur * DD + ch], acc);
}

// segmented pooling for layer-0 (h = x, no BN)
__global__ void k_gpool(float* __restrict__ pg, const float* __restrict__ h,
                        const int* __restrict__ gids) {
    int warp = (blockIdx.x * blockDim.x + threadIdx.x) >> 5;
    int lane = threadIdx.x & 31;
    int r0 = warp * 32;
    if (r0 >= NND) return;
    int r1 = min(r0 + 32, NND);
    int ch = lane * 4;
    int cur = __ldg(&gids[r0]);
    float4 acc = make_float4(0.f, 0.f, 0.f, 0.f);
    for (int r = r0; r < r1; r++) {
        int gid = __ldg(&gids[r]);
        if (gid != cur) {
            red_add_v4(&pg[cur * DD + ch], acc);
            acc = make_float4(0.f, 0.f, 0.f, 0.f);
            cur = gid;
        }
        float4 v = ((const float4*)h)[r * 32 + lane];
        acc.x += v.x; acc.y += v.y; acc.z += v.z; acc.w += v.w;
    }
    red_add_v4(&pg[cur * DD + ch], acc);
}

__global__ void k_readout(float* __restrict__ out,
                          const float* __restrict__ predW,
                          const float* __restrict__ predb) {
    int g = blockIdx.x;
    int o = threadIdx.x;
    float acc = 0.f;
#pragma unroll
    for (int l = 0; l < NL + 1; l++) {
        const float* pgrow = &g_pg[l * NG * DD + g * DD];
        const float* Wl = &predW[l * DD * OUTD];
        float a = 0.f;
        for (int k = 0; k < DD; k++)
            a += pgrow[k] * __ldg(&Wl[k * OUTD + o]);
        acc += a + __ldg(&predb[l * OUTD + o]);
    }
    out[g * OUTD + o] = acc;
}

// ---------------- launch ----------------
extern "C" void kernel_launch(void* const* d_in, const int* in_sizes, int n_in,
                              void* d_out, int out_size) {
    const float* x     = (const float*)d_in[0];
    const int* esrc    = (const int*)d_in[1];
    const int* edst    = (const int*)d_in[2];
    const int* gids    = (const int*)d_in[3];
    const float* eps   = (const float*)d_in[4];
    const float* W1    = (const float*)d_in[5];
    const float* b1    = (const float*)d_in[6];
    const float* g1    = (const float*)d_in[7];
    const float* be1   = (const float*)d_in[8];
    const float* W2    = (const float*)d_in[9];
    const float* b2    = (const float*)d_in[10];
    const float* g2    = (const float*)d_in[11];
    const float* be2   = (const float*)d_in[12];
    const float* predW = (const float*)d_in[13];
    const float* predb = (const float*)d_in[14];
    float* out = (float*)d_out;

    float *P, *Z, *Z2, *stats, *pg;
    int* deg;
    cudaGetSymbolAddress((void**)&P, g_P);
    cudaGetSymbolAddress((void**)&Z, g_Z);
    cudaGetSymbolAddress((void**)&Z2, g_Z2);
    cudaGetSymbolAddress((void**)&stats, g_stats);
    cudaGetSymbolAddress((void**)&pg, g_pg);
    cudaGetSymbolAddress((void**)&deg, g_deg);
    float* s0 = stats;
    float* s1 = stats + 2 * DD;

    const int smem_mm = 4 * DD * AST * (int)sizeof(unsigned short) + 65536;  // 200704
    static bool attr_set = false;
    if (!attr_set) {
        cudaFuncSetAttribute(k_mm, cudaFuncAttributeMaxDynamicSharedMemorySize, smem_mm);
        attr_set = true;
    }

    const int gridEdge = (NE + 255) / 256;
    const int nWarps = (NND + 31) / 32;
    const int gridSeg = (nWarps * 32 + 255) / 256;

    // CSR build (once; shared by all 4 layers)
    cudaMemsetAsync(deg, 0, sizeof(int) * NND);
    k_hist<<<gridEdge, 256>>>(edst);
    k_scan<<<1, 1024>>>();
    k_scatter<<<gridEdge, 256>>>(esrc, edst);

    // layer-0 graph pooling
    cudaMemsetAsync(pg, 0, sizeof(float) * (NL + 1) * NG * DD);
    k_gpool<<<gridSeg, 256>>>(pg, x, gids);

    for (int l = 0; l < NL; l++) {
        if (l == 0)
            k_agg<<<(NND + 7) / 8, 256>>>(P, x, eps, l, nullptr, nullptr, nullptr);
        else
            k_agg<<<(NND + 7) / 8, 256>>>(P, Z2, eps, l,
                                          g2 + (l - 1) * DD, be2 + (l - 1) * DD, s1);

        cudaMemsetAsync(s0, 0, sizeof(float) * 2 * DD);
        k_mm<<<148, 256, smem_mm>>>(Z, P, W1 + l * DD * DD, b1 + l * DD,
                                    nullptr, nullptr, nullptr, s0);

        cudaMemsetAsync(s1, 0, sizeof(float) * 2 * DD);
        k_mm<<<148, 256, smem_mm>>>(Z2, Z, W2 + l * DD * DD, b2 + l * DD,
                                    g1 + l * DD, be1 + l * DD, s0, s1);

        k_pool<<<gridSeg, 256>>>(pg + (l + 1) * NG * DD, Z2,
                                 g2 + l * DD, be2 + l * DD, s1, gids);
    }

    k_readout<<<NG, OUTD>>>(out, predW, predb);
}

// round 13
// speedup vs baseline: 1.3136x; 1.0714x over previous
#include <cuda_runtime.h>
#include <cuda_bf16.h>
#include <cuda_fp16.h>

#define NND 100000
#define NE  1600000
#define NG  128
#define DD  128
#define OUTD 64
#define NL  4
#define BN_EPS 1e-5f
#define NT  782                    // ceil(NND/128)
#define AST 132                    // smem row stride in bf16 elems

// ---------------- scratch (device globals; no allocation) ----------------
__device__ float g_P[NND * DD];
__device__ float g_Z[NND * DD];     // GEMM1 output
__device__ float g_Z2[NND * DD];    // GEMM2 output
__device__ unsigned short g_H16[NND * DD];   // fp16 activation image (gather source)
__device__ float g_stats[2][2 * DD];
__device__ float g_pg[(NL + 1) * NG * DD];
__device__ int   g_deg[NND];
__device__ int   g_off[NND + 1];
__device__ int   g_cur[NND];
__device__ int   g_esrt[NE];

// ---------------- helpers ----------------
__device__ __forceinline__ void red_add_v4(float* addr, float4 v) {
    asm volatile("red.global.add.v4.f32 [%0], {%1, %2, %3, %4};"
                 :: "l"(addr), "f"(v.x), "f"(v.y), "f"(v.z), "f"(v.w) : "memory");
}
__device__ __forceinline__ unsigned cvt2bf(float lo, float hi) {
    unsigned r;
    asm("cvt.rn.bf16x2.f32 %0, %1, %2;" : "=r"(r) : "f"(hi), "f"(lo));
    return r;
}
__device__ __forceinline__ uint2 pack_h4(float4 v) {   // 4 floats -> 4 fp16
    __half2 a = __floats2half2_rn(v.x, v.y);
    __half2 b = __floats2half2_rn(v.z, v.w);
    return make_uint2(*(unsigned*)&a, *(unsigned*)&b);
}
__device__ __forceinline__ float4 unpack_h4(uint2 p) {
    float2 a = __half22float2(*(__half2*)&p.x);
    float2 b = __half22float2(*(__half2*)&p.y);
    return make_float4(a.x, a.y, b.x, b.y);
}
__device__ __forceinline__ void mma16816(float* c, const unsigned* a, const unsigned* b) {
    asm volatile("mma.sync.aligned.m16n8k16.row.col.f32.bf16.bf16.f32 "
                 "{%0,%1,%2,%3}, {%4,%5,%6,%7}, {%8,%9}, {%0,%1,%2,%3};"
                 : "+f"(c[0]), "+f"(c[1]), "+f"(c[2]), "+f"(c[3])
                 : "r"(a[0]), "r"(a[1]), "r"(a[2]), "r"(a[3]), "r"(b[0]), "r"(b[1]));
}
__device__ __forceinline__ void cpasync16(unsigned saddr, const void* g, int sz) {
    asm volatile("cp.async.cg.shared.global [%0], [%1], 16, %2;"
                 :: "r"(saddr), "l"(g), "r"(sz) : "memory");
}
#define CP_COMMIT() asm volatile("cp.async.commit_group;" ::: "memory")
#define CP_WAIT0()  asm volatile("cp.async.wait_group 0;" ::: "memory")

// ---------------- CSR build ----------------
__global__ void k_hist(const int* __restrict__ dst) {
    int e = blockIdx.x * blockDim.x + threadIdx.x;
    if (e < NE) atomicAdd(&g_deg[__ldg(&dst[e])], 1);
}
__global__ void k_scan() {
    __shared__ int sp[1024];
    int t = threadIdx.x;
    int base = t * 98;
    int s = 0;
    for (int i = 0; i < 98; i++) { int j = base + i; if (j < NND) s += g_deg[j]; }
    sp[t] = s;
    __syncthreads();
    for (int o = 1; o < 1024; o <<= 1) {
        int v = (t >= o) ? sp[t - o] : 0;
        __syncthreads();
        sp[t] += v;
        __syncthreads();
    }
    int run = t ? sp[t - 1] : 0;
    for (int i = 0; i < 98; i++) {
        int j = base + i;
        if (j < NND) { g_off[j] = run; g_cur[j] = run; run += g_deg[j]; }
    }
    if (t == 0) g_off[NND] = NE;
}
__global__ void k_scatter(const int* __restrict__ src, const int* __restrict__ dst) {
    int e = blockIdx.x * blockDim.x + threadIdx.x;
    if (e >= NE) return;
    int pos = atomicAdd(&g_cur[__ldg(&dst[e])], 1);
    g_esrt[pos] = __ldg(&src[e]);
}

// ---- aggregation: pure gather+sum from fp16 image.
// P[d] = (1+eps) * h16[d] + sum_{e: dst=d} h16[src[e]]
__global__ void k_agg(float* __restrict__ P, const unsigned short* __restrict__ H16,
                      const float* __restrict__ eps, int l) {
    int gw = (blockIdx.x * blockDim.x + threadIdx.x) >> 5;
    int lane = threadIdx.x & 31;
    if (gw >= NND) return;
    int ch = lane * 4;
    int e0 = __ldg(&g_off[gw]), e1 = __ldg(&g_off[gw + 1]);
    float e = 1.0f + __ldg(&eps[l]);

    const uint2* H = (const uint2*)H16;   // 8B per lane-chunk; row stride = 32
    float4 v = unpack_h4(__ldg(H + (size_t)gw * 32 + lane));
    float4 acc = make_float4(v.x * e, v.y * e, v.z * e, v.w * e);
    int i = e0;
    for (; i + 1 < e1; i += 2) {
        int x0 = __ldg(&g_esrt[i]), x1 = __ldg(&g_esrt[i + 1]);
        float4 a0 = unpack_h4(__ldg(H + (size_t)x0 * 32 + lane));
        float4 a1 = unpack_h4(__ldg(H + (size_t)x1 * 32 + lane));
        acc.x += a0.x + a1.x; acc.y += a0.y + a1.y;
        acc.z += a0.z + a1.z; acc.w += a0.w + a1.w;
    }
    if (i < e1) {
        int x0 = __ldg(&g_esrt[i]);
        float4 a0 = unpack_h4(__ldg(H + (size_t)x0 * 32 + lane));
        acc.x += a0.x; acc.y += a0.y; acc.z += a0.z; acc.w += a0.w;
    }
    __stcs((float4*)P + gw * 32 + lane, acc);
}

// ---------------- HMMA bf16x3 GEMM, cp.async-staged, fused stats & input-BN ----------
__global__ void __launch_bounds__(256, 1)
k_mm(float* __restrict__ Z, const float* __restrict__ A,
     const float* __restrict__ W, const float* __restrict__ bias,
     const float* __restrict__ gam, const float* __restrict__ bet,
     const float* __restrict__ statsIn, float* __restrict__ statsOut) {
    extern __shared__ unsigned short sm[];
    unsigned short* Whi = sm;
    unsigned short* Wlo = sm + DD * AST;
    unsigned short* Ahi = sm + 2 * DD * AST;
    unsigned short* Alo = sm + 3 * DD * AST;
    float* Sg = (float*)(sm + 4 * DD * AST);
    __shared__ float colsum[DD], colsq[DD], bias_s[DD], scA[DD], shA[DD];

    const int t = threadIdx.x;
    const int w = t >> 5, lane = t & 31;
    const int g = lane >> 2, q = lane & 3;
    const int wr = (w & 3) * 32;
    const int wc = (w >> 2) * 64;
    const bool doBN = (gam != nullptr);
    const unsigned sgBase = (unsigned)__cvta_generic_to_shared(Sg);

    {
        int ti = blockIdx.x;
#pragma unroll
        for (int i = 0; i < 16; i++) {
            int fi = t + i * 256;
            int row = fi >> 5, kq = fi & 31;
            int grow = ti * 128 + row;
            bool valid = grow < NND;
            const float4* gp = (const float4*)A + ((size_t)(valid ? grow : 0) * 32 + kq);
            cpasync16(sgBase + fi * 16, gp, valid ? 16 : 0);
        }
        CP_COMMIT();
    }

    for (int e = t; e < DD * DD; e += 256) {
        int k = e >> 7, n = e & 127;
        float x = __ldg(&W[k * DD + n]);
        unsigned xu = __float_as_uint(x);
        Whi[n * AST + k] = (unsigned short)(xu >> 16);
        unsigned lp = cvt2bf(x - __uint_as_float(xu & 0xffff0000u), 0.f);
        Wlo[n * AST + k] = (unsigned short)(lp & 0xffff);
    }
    if (t < DD) {
        colsum[t] = 0.f; colsq[t] = 0.f; bias_s[t] = __ldg(&bias[t]);
        if (doBN) {
            const float inv_n = 1.0f / (float)NND;
            float mu = statsIn[t] * inv_n;
            float var = statsIn[DD + t] * inv_n - mu * mu;
            float s = __ldg(&gam[t]) * rsqrtf(var + BN_EPS);
            scA[t] = s;
            shA[t] = __ldg(&bet[t]) - mu * s;
        }
    }

    for (int ti = blockIdx.x; ti < NT; ti += gridDim.x) {
        CP_WAIT0();
        __syncthreads();

#pragma unroll
        for (int i = 0; i < 16; i++) {
            int fi = t + i * 256;
            int row = fi >> 5, kq = fi & 31;
            float4 v = ((const float4*)Sg)[fi];
            if (doBN) {
                int ch = kq * 4;
                v.x = fmaxf(v.x * scA[ch] + shA[ch], 0.f);
                v.y = fmaxf(v.y * scA[ch + 1] + shA[ch + 1], 0.f);
                v.z = fmaxf(v.z * scA[ch + 2] + shA[ch + 2], 0.f);
                v.w = fmaxf(v.w * scA[ch + 3] + shA[ch + 3], 0.f);
            }
            unsigned hx = __byte_perm(__float_as_uint(v.x), __float_as_uint(v.y), 0x7632);
            unsigned hy = __byte_perm(__float_as_uint(v.z), __float_as_uint(v.w), 0x7632);
            unsigned lx = cvt2bf(v.x - __uint_as_float(__float_as_uint(v.x) & 0xffff0000u),
                                 v.y - __uint_as_float(__float_as_uint(v.y) & 0xffff0000u));
            unsigned ly = cvt2bf(v.z - __uint_as_float(__float_as_uint(v.z) & 0xffff0000u),
                                 v.w - __uint_as_float(__float_as_uint(v.w) & 0xffff0000u));
            *(uint2*)&Ahi[row * AST + kq * 4] = make_uint2(hx, hy);
            *(uint2*)&Alo[row * AST + kq * 4] = make_uint2(lx, ly);
        }
        __syncthreads();

        int tn = ti + gridDim.x;
        if (tn < NT) {
#pragma unroll
            for (int i = 0; i < 16; i++) {
                int fi = t + i * 256;
                int row = fi >> 5, kq = fi & 31;
                int grow = tn * 128 + row;
                bool valid = grow < NND;
                const float4* gp = (const float4*)A + ((size_t)(valid ? grow : 0) * 32 + kq);
                cpasync16(sgBase + fi * 16, gp, valid ? 16 : 0);
            }
            CP_COMMIT();
        }

        float c[16][4];
#pragma unroll
        for (int i = 0; i < 16; i++)
#pragma unroll
            for (int j = 0; j < 4; j++) c[i][j] = 0.f;

#pragma unroll
        for (int ks = 0; ks < 8; ks++) {
            int k0 = ks * 16;
            unsigned ah[2][4], al[2][4];
#pragma unroll
            for (int m = 0; m < 2; m++) {
                int r0 = wr + m * 16;
                ah[m][0] = *(unsigned*)&Ahi[(r0 + g) * AST + k0 + q * 2];
                ah[m][1] = *(unsigned*)&Ahi[(r0 + g + 8) * AST + k0 + q * 2];
                ah[m][2] = *(unsigned*)&Ahi[(r0 + g) * AST + k0 + 8 + q * 2];
                ah[m][3] = *(unsigned*)&Ahi[(r0 + g + 8) * AST + k0 + 8 + q * 2];
                al[m][0] = *(unsigned*)&Alo[(r0 + g) * AST + k0 + q * 2];
                al[m][1] = *(unsigned*)&Alo[(r0 + g + 8) * AST + k0 + q * 2];
                al[m][2] = *(unsigned*)&Alo[(r0 + g) * AST + k0 + 8 + q * 2];
                al[m][3] = *(unsigned*)&Alo[(r0 + g + 8) * AST + k0 + 8 + q * 2];
            }
            unsigned bh[8][2], bl[8][2];
#pragma unroll
            for (int n = 0; n < 8; n++) {
                int n0 = wc + n * 8 + g;
                bh[n][0] = *(unsigned*)&Whi[n0 * AST + k0 + q * 2];
                bh[n][1] = *(unsigned*)&Whi[n0 * AST + k0 + 8 + q * 2];
                bl[n][0] = *(unsigned*)&Wlo[n0 * AST + k0 + q * 2];
                bl[n][1] = *(unsigned*)&Wlo[n0 * AST + k0 + 8 + q * 2];
            }
#pragma unroll
            for (int m = 0; m < 2; m++)
#pragma unroll
                for (int n = 0; n < 8; n++) {
                    mma16816(c[m * 8 + n], ah[m], bh[n]);
                    mma16816(c[m * 8 + n], al[m], bh[n]);
                    mma16816(c[m * 8 + n], ah[m], bl[n]);
                }
        }

#pragma unroll
        for (int n = 0; n < 8; n++) {
            int col = wc + n * 8 + q * 2;
            float b0 = bias_s[col], b1 = bias_s[col + 1];
            float s0 = 0.f, s1 = 0.f, q0 = 0.f, q1 = 0.f;
#pragma unroll
            for (int m = 0; m < 2; m++) {
                int row0 = ti * 128 + wr + m * 16 + g;
                float* cf = c[m * 8 + n];
                float v0 = cf[0] + b0, v1 = cf[1] + b1;
                float v2 = cf[2] + b0, v3 = cf[3] + b1;
                if (row0 < NND) {
                    *(float2*)&Z[(size_t)row0 * DD + col] = make_float2(v0, v1);
                    s0 += v0; s1 += v1; q0 += v0 * v0; q1 += v1 * v1;
                }
                if (row0 + 8 < NND) {
                    *(float2*)&Z[(size_t)(row0 + 8) * DD + col] = make_float2(v2, v3);
                    s0 += v2; s1 += v3; q0 += v2 * v2; q1 += v3 * v3;
                }
            }
#pragma unroll
            for (int o = 4; o < 32; o <<= 1) {
                s0 += __shfl_xor_sync(0xffffffffu, s0, o);
                s1 += __shfl_xor_sync(0xffffffffu, s1, o);
                q0 += __shfl_xor_sync(0xffffffffu, q0, o);
                q1 += __shfl_xor_sync(0xffffffffu, q1, o);
            }
            if (lane < 4) {
                atomicAdd(&colsum[col], s0);
                atomicAdd(&colsum[col + 1], s1);
                atomicAdd(&colsq[col], q0);
                atomicAdd(&colsq[col + 1], q1);
            }
        }
    }

    __syncthreads();
    if (t < DD) {
        atomicAdd(&statsOut[t], colsum[t]);
        atomicAdd(&statsOut[DD + t], colsq[t]);
    }
}

// ---------------- BN-on-the-fly segmented pooling + fp16 image write ----------------
__global__ void k_pool(float* __restrict__ pg, const float* __restrict__ Z,
                       const float* __restrict__ gam, const float* __restrict__ bet,
                       const float* __restrict__ stats, const int* __restrict__ gids,
                       unsigned short* __restrict__ H16, int writeH) {
    __shared__ float sc[DD], sh[DD];
    int t = threadIdx.x;
    if (t < DD) {
        const float inv_n = 1.0f / (float)NND;
        float mu = stats[t] * inv_n;
        float var = stats[DD + t] * inv_n - mu * mu;
        float s = __ldg(&gam[t]) * rsqrtf(var + BN_EPS);
        sc[t] = s;
        sh[t] = __ldg(&bet[t]) - mu * s;
    }
    __syncthreads();
    int warp = (blockIdx.x * blockDim.x + t) >> 5;
    int lane = t & 31;
    int r0 = warp * 32;
    if (r0 >= NND) return;
    int r1 = min(r0 + 32, NND);
    int ch = lane * 4;
    float c0 = sc[ch], c1 = sc[ch + 1], c2 = sc[ch + 2], c3 = sc[ch + 3];
    float h0 = sh[ch], h1 = sh[ch + 1], h2 = sh[ch + 2], h3 = sh[ch + 3];
    int cur = __ldg(&gids[r0]);
    float4 acc = make_float4(0.f, 0.f, 0.f, 0.f);
    for (int r = r0; r < r1; r++) {
        int gid = __ldg(&gids[r]);
        if (gid != cur) {
            red_add_v4(&pg[cur * DD + ch], acc);
            acc = make_float4(0.f, 0.f, 0.f, 0.f);
            cur = gid;
        }
        float4 v = ((const float4*)Z)[r * 32 + lane];
        float4 a;
        a.x = fmaxf(v.x * c0 + h0, 0.f);
        a.y = fmaxf(v.y * c1 + h1, 0.f);
        a.z = fmaxf(v.z * c2 + h2, 0.f);
        a.w = fmaxf(v.w * c3 + h3, 0.f);
        if (writeH) ((uint2*)H16)[(size_t)r * 32 + lane] = pack_h4(a);
        acc.x += a.x; acc.y += a.y; acc.z += a.z; acc.w += a.w;
    }
    red_add_v4(&pg[cur * DD + ch], acc);
}

// segmented pooling for layer-0 (h = x) + fp16 image of x
__global__ void k_gpool(float* __restrict__ pg, const float* __restrict__ h,
                        const int* __restrict__ gids, unsigned short* __restrict__ H16) {
    int warp = (blockIdx.x * blockDim.x + threadIdx.x) >> 5;
    int lane = threadIdx.x & 31;
    int r0 = warp * 32;
    if (r0 >= NND) return;
    int r1 = min(r0 + 32, NND);
    int ch = lane * 4;
    int cur = __ldg(&gids[r0]);
    float4 acc = make_float4(0.f, 0.f, 0.f, 0.f);
    for (int r = r0; r < r1; r++) {
        int gid = __ldg(&gids[r]);
        if (gid != cur) {
            red_add_v4(&pg[cur * DD + ch], acc);
            acc = make_float4(0.f, 0.f, 0.f, 0.f);
            cur = gid;
        }
        float4 v = ((const float4*)h)[r * 32 + lane];
        ((uint2*)H16)[(size_t)r * 32 + lane] = pack_h4(v);
        acc.x += v.x; acc.y += v.y; acc.z += v.z; acc.w += v.w;
    }
    red_add_v4(&pg[cur * DD + ch], acc);
}

__global__ void k_readout(float* __restrict__ out,
                          const float* __restrict__ predW,
                          const float* __restrict__ predb) {
    int g = blockIdx.x;
    int o = threadIdx.x;
    float acc = 0.f;
#pragma unroll
    for (int l = 0; l < NL + 1; l++) {
        const float* pgrow = &g_pg[l * NG * DD + g * DD];
        const float* Wl = &predW[l * DD * OUTD];
        float a = 0.f;
        for (int k = 0; k < DD; k++)
            a += pgrow[k] * __ldg(&Wl[k * OUTD + o]);
        acc += a + __ldg(&predb[l * OUTD + o]);
    }
    out[g * OUTD + o] = acc;
}

// ---------------- launch ----------------
extern "C" void kernel_launch(void* const* d_in, const int* in_sizes, int n_in,
                              void* d_out, int out_size) {
    const float* x     = (const float*)d_in[0];
    const int* esrc    = (const int*)d_in[1];
    const int* edst    = (const int*)d_in[2];
    const int* gids    = (const int*)d_in[3];
    const float* eps   = (const float*)d_in[4];
    const float* W1    = (const float*)d_in[5];
    const float* b1    = (const float*)d_in[6];
    const float* g1    = (const float*)d_in[7];
    const float* be1   = (const float*)d_in[8];
    const float* W2    = (const float*)d_in[9];
    const float* b2    = (const float*)d_in[10];
    const float* g2    = (const float*)d_in[11];
    const float* be2   = (const float*)d_in[12];
    const float* predW = (const float*)d_in[13];
    const float* predb = (const float*)d_in[14];
    float* out = (float*)d_out;

    float *P, *Z, *Z2, *stats, *pg;
    unsigned short* H16;
    int* deg;
    cudaGetSymbolAddress((void**)&P, g_P);
    cudaGetSymbolAddress((void**)&Z, g_Z);
    cudaGetSymbolAddress((void**)&Z2, g_Z2);
    cudaGetSymbolAddress((void**)&H16, g_H16);
    cudaGetSymbolAddress((void**)&stats, g_stats);
    cudaGetSymbolAddress((void**)&pg, g_pg);
    cudaGetSymbolAddress((void**)&deg, g_deg);
    float* s0 = stats;
    float* s1 = stats + 2 * DD;

    const int smem_mm = 4 * DD * AST * (int)sizeof(unsigned short) + 65536;  // 200704
    static bool attr_set = false;
    if (!attr_set) {
        cudaFuncSetAttribute(k_mm, cudaFuncAttributeMaxDynamicSharedMemorySize, smem_mm);
        attr_set = true;
    }

    const int gridEdge = (NE + 255) / 256;
    const int nWarps = (NND + 31) / 32;
    const int gridSeg = (nWarps * 32 + 255) / 256;

    // CSR build (once; shared by all 4 layers)
    cudaMemsetAsync(deg, 0, sizeof(int) * NND);
    k_hist<<<gridEdge, 256>>>(edst);
    k_scan<<<1, 1024>>>();
    k_scatter<<<gridEdge, 256>>>(esrc, edst);

    // layer-0 graph pooling + fp16 image of x
    cudaMemsetAsync(pg, 0, sizeof(float) * (NL + 1) * NG * DD);
    k_gpool<<<gridSeg, 256>>>(pg, x, gids, H16);

    for (int l = 0; l < NL; l++) {
        k_agg<<<(NND + 7) / 8, 256>>>(P, H16, eps, l);

        cudaMemsetAsync(s0, 0, sizeof(float) * 2 * DD);
        k_mm<<<148, 256, smem_mm>>>(Z, P, W1 + l * DD * DD, b1 + l * DD,
                                    nullptr, nullptr, nullptr, s0);

        cudaMemsetAsync(s1, 0, sizeof(float) * 2 * DD);
        k_mm<<<148, 256, smem_mm>>>(Z2, Z, W2 + l * DD * DD, b2 + l * DD,
                                    g1 + l * DD, be1 + l * DD, s0, s1);

        k_pool<<<gridSeg, 256>>>(pg + (l + 1) * NG * DD, Z2,
                                 g2 + l * DD, be2 + l * DD, s1, gids,
                                 H16, l < NL - 1 ? 1 : 0);
    }

    k_readout<<<NG, OUTD>>>(out, predW, predb);
}

// round 14
// speedup vs baseline: 1.4050x; 1.0696x over previous
#include <cuda_runtime.h>
#include <cuda_bf16.h>
#include <cuda_fp16.h>

#define NND 100000
#define NE  1600000
#define NG  128
#define DD  128
#define OUTD 64
#define NL  4
#define BN_EPS 1e-5f
#define NT  782                    // ceil(NND/128)
#define AST 132                    // smem row stride in fp16 elems

// ---------------- scratch (device globals; no allocation) ----------------
__device__ float g_P[NND * DD];     // reused as fp16 P image
__device__ float g_Z[NND * DD];     // reused as fp16 GEMM1 output
__device__ float g_Z2[NND * DD];    // fp32 GEMM2 output
__device__ unsigned short g_H16[NND * DD];   // fp16 activation image (gather source)
__device__ float g_stats[2][2 * DD];
__device__ float g_pg[(NL + 1) * NG * DD];
__device__ int   g_deg[NND];
__device__ int   g_off[NND + 1];
__device__ int   g_cur[NND];
__device__ int   g_esrt[NE];

// ---------------- helpers ----------------
__device__ __forceinline__ void red_add_v4(float* addr, float4 v) {
    asm volatile("red.global.add.v4.f32 [%0], {%1, %2, %3, %4};"
                 :: "l"(addr), "f"(v.x), "f"(v.y), "f"(v.z), "f"(v.w) : "memory");
}
__device__ __forceinline__ uint2 pack_h4(float4 v) {   // 4 floats -> 4 fp16
    __half2 a = __floats2half2_rn(v.x, v.y);
    __half2 b = __floats2half2_rn(v.z, v.w);
    return make_uint2(*(unsigned*)&a, *(unsigned*)&b);
}
__device__ __forceinline__ float4 unpack_h4(uint2 p) {
    float2 a = __half22float2(*(__half2*)&p.x);
    float2 b = __half22float2(*(__half2*)&p.y);
    return make_float4(a.x, a.y, b.x, b.y);
}
__device__ __forceinline__ void mma16816f16(float* c, const unsigned* a, const unsigned* b) {
    asm volatile("mma.sync.aligned.m16n8k16.row.col.f32.f16.f16.f32 "
                 "{%0,%1,%2,%3}, {%4,%5,%6,%7}, {%8,%9}, {%0,%1,%2,%3};"
                 : "+f"(c[0]), "+f"(c[1]), "+f"(c[2]), "+f"(c[3])
                 : "r"(a[0]), "r"(a[1]), "r"(a[2]), "r"(a[3]), "r"(b[0]), "r"(b[1]));
}
__device__ __forceinline__ void cpasync16(unsigned saddr, const void* g, int sz) {
    asm volatile("cp.async.cg.shared.global [%0], [%1], 16, %2;"
                 :: "r"(saddr), "l"(g), "r"(sz) : "memory");
}
#define CP_COMMIT() asm volatile("cp.async.commit_group;" ::: "memory")
#define CP_WAIT0()  asm volatile("cp.async.wait_group 0;" ::: "memory")

// ---------------- CSR build ----------------
__global__ void k_hist(const int* __restrict__ dst) {
    int e = blockIdx.x * blockDim.x + threadIdx.x;
    if (e < NE) atomicAdd(&g_deg[__ldg(&dst[e])], 1);
}
__global__ void k_scan() {
    __shared__ int sp[1024];
    int t = threadIdx.x;
    int base = t * 98;
    int s = 0;
    for (int i = 0; i < 98; i++) { int j = base + i; if (j < NND) s += g_deg[j]; }
    sp[t] = s;
    __syncthreads();
    for (int o = 1; o < 1024; o <<= 1) {
        int v = (t >= o) ? sp[t - o] : 0;
        __syncthreads();
        sp[t] += v;
        __syncthreads();
    }
    int run = t ? sp[t - 1] : 0;
    for (int i = 0; i < 98; i++) {
        int j = base + i;
        if (j < NND) { g_off[j] = run; g_cur[j] = run; run += g_deg[j]; }
    }
    if (t == 0) g_off[NND] = NE;
}
__global__ void k_scatter(const int* __restrict__ src, const int* __restrict__ dst) {
    int e = blockIdx.x * blockDim.x + threadIdx.x;
    if (e >= NE) return;
    int pos = atomicAdd(&g_cur[__ldg(&dst[e])], 1);
    g_esrt[pos] = __ldg(&src[e]);
}

// ---- aggregation: gather+sum from fp16 image, write fp16 P.
__global__ void k_agg(unsigned short* __restrict__ P16,
                      const unsigned short* __restrict__ H16,
                      const float* __restrict__ eps, int l) {
    int gw = (blockIdx.x * blockDim.x + threadIdx.x) >> 5;
    int lane = threadIdx.x & 31;
    if (gw >= NND) return;
    int e0 = __ldg(&g_off[gw]), e1 = __ldg(&g_off[gw + 1]);
    float e = 1.0f + __ldg(&eps[l]);

    const uint2* H = (const uint2*)H16;
    float4 v = unpack_h4(__ldg(H + (size_t)gw * 32 + lane));
    float4 acc = make_float4(v.x * e, v.y * e, v.z * e, v.w * e);
    int i = e0;
    for (; i + 1 < e1; i += 2) {
        int x0 = __ldg(&g_esrt[i]), x1 = __ldg(&g_esrt[i + 1]);
        float4 a0 = unpack_h4(__ldg(H + (size_t)x0 * 32 + lane));
        float4 a1 = unpack_h4(__ldg(H + (size_t)x1 * 32 + lane));
        acc.x += a0.x + a1.x; acc.y += a0.y + a1.y;
        acc.z += a0.z + a1.z; acc.w += a0.w + a1.w;
    }
    if (i < e1) {
        int x0 = __ldg(&g_esrt[i]);
        float4 a0 = unpack_h4(__ldg(H + (size_t)x0 * 32 + lane));
        acc.x += a0.x; acc.y += a0.y; acc.z += a0.z; acc.w += a0.w;
    }
    ((uint2*)P16)[(size_t)gw * 32 + lane] = pack_h4(acc);
}

// ---------------- fp16 HMMA GEMM (A exact fp16, W 2-term fp16 split) ----------------
// in: fp16 [NND,128]; out: fp16 or fp32; optional input-BN (fp32 math); fused out-stats.
__global__ void __launch_bounds__(256, 1)
k_mm(void* __restrict__ Zout, const unsigned short* __restrict__ Ain,
     const float* __restrict__ W, const float* __restrict__ bias,
     const float* __restrict__ gam, const float* __restrict__ bet,
     const float* __restrict__ statsIn, float* __restrict__ statsOut, int outFp16) {
    extern __shared__ unsigned short sm[];
    unsigned short* Wh = sm;                 // fp16 hi [DD][AST]
    unsigned short* Wl = sm + DD * AST;      // fp16 lo
    unsigned short* At = sm + 2 * DD * AST;  // fp16 A tile
    char* Sg = (char*)(sm + 3 * DD * AST);   // 32KB fp16 staging
    __shared__ float colsum[DD], colsq[DD], bias_s[DD], scA[DD], shA[DD];

    const int t = threadIdx.x;
    const int w = t >> 5, lane = t & 31;
    const int g = lane >> 2, q = lane & 3;
    const int wr = (w & 3) * 32;
    const int wc = (w >> 2) * 64;
    const bool doBN = (gam != nullptr);
    const unsigned sgBase = (unsigned)__cvta_generic_to_shared(Sg);

    // first tile staging fetch (fp16 rows: 256B = 16 x 16B chunks)
    {
        int ti = blockIdx.x;
#pragma unroll
        for (int i = 0; i < 8; i++) {
            int fi = t + i * 256;          // [0,2048)
            int row = fi >> 4, ck = fi & 15;
            int grow = ti * 128 + row;
            bool valid = grow < NND;
            const uint4* gp = (const uint4*)Ain + ((size_t)(valid ? grow : 0) * 16 + ck);
            cpasync16(sgBase + fi * 16, gp, valid ? 16 : 0);
        }
        CP_COMMIT();
    }

    // prologue: W split to fp16 hi/lo (B[n][k] = W[k][n]), bias, stats, BN coefs
    for (int e = t; e < DD * DD; e += 256) {
        int k = e >> 7, n = e & 127;
        float x = __ldg(&W[k * DD + n]);
        __half hx = __float2half_rn(x);
        __half lx = __float2half_rn(x - __half2float(hx));
        Wh[n * AST + k] = *(unsigned short*)&hx;
        Wl[n * AST + k] = *(unsigned short*)&lx;
    }
    if (t < DD) {
        colsum[t] = 0.f; colsq[t] = 0.f; bias_s[t] = __ldg(&bias[t]);
        if (doBN) {
            const float inv_n = 1.0f / (float)NND;
            float mu = statsIn[t] * inv_n;
            float var = statsIn[DD + t] * inv_n - mu * mu;
            float s = __ldg(&gam[t]) * rsqrtf(var + BN_EPS);
            scA[t] = s;
            shA[t] = __ldg(&bet[t]) - mu * s;
        }
    }

    for (int ti = blockIdx.x; ti < NT; ti += gridDim.x) {
        CP_WAIT0();
        __syncthreads();

        // convert staging -> A tile (optional BN+relu in fp32)
#pragma unroll
        for (int i = 0; i < 16; i++) {
            int fi = t + i * 256;              // [0,4096) uint2 (4 halfs) units
            int row = fi >> 5, kq = fi & 31;
            uint2 p = ((const uint2*)Sg)[fi];
            if (doBN) {
                float4 v = unpack_h4(p);
                int ch = kq * 4;
                v.x = fmaxf(v.x * scA[ch] + shA[ch], 0.f);
                v.y = fmaxf(v.y * scA[ch + 1] + shA[ch + 1], 0.f);
                v.z = fmaxf(v.z * scA[ch + 2] + shA[ch + 2], 0.f);
                v.w = fmaxf(v.w * scA[ch + 3] + shA[ch + 3], 0.f);
                p = pack_h4(v);
            }
            *(uint2*)&At[row * AST + kq * 4] = p;
        }
        __syncthreads();

        // prefetch next tile
        int tn = ti + gridDim.x;
        if (tn < NT) {
#pragma unroll
            for (int i = 0; i < 8; i++) {
                int fi = t + i * 256;
                int row = fi >> 4, ck = fi & 15;
                int grow = tn * 128 + row;
                bool valid = grow < NND;
                const uint4* gp = (const uint4*)Ain + ((size_t)(valid ? grow : 0) * 16 + ck);
                cpasync16(sgBase + fi * 16, gp, valid ? 16 : 0);
            }
            CP_COMMIT();
        }

        float c[16][4];
#pragma unroll
        for (int i = 0; i < 16; i++)
#pragma unroll
            for (int j = 0; j < 4; j++) c[i][j] = 0.f;

#pragma unroll
        for (int ks = 0; ks < 8; ks++) {
            int k0 = ks * 16;
            unsigned a[2][4];
#pragma unroll
            for (int m = 0; m < 2; m++) {
                int r0 = wr + m * 16;
                a[m][0] = *(unsigned*)&At[(r0 + g) * AST + k0 + q * 2];
                a[m][1] = *(unsigned*)&At[(r0 + g + 8) * AST + k0 + q * 2];
                a[m][2] = *(unsigned*)&At[(r0 + g) * AST + k0 + 8 + q * 2];
                a[m][3] = *(unsigned*)&At[(r0 + g + 8) * AST + k0 + 8 + q * 2];
            }
            unsigned bh[8][2], bl[8][2];
#pragma unroll
            for (int n = 0; n < 8; n++) {
                int n0 = wc + n * 8 + g;
                bh[n][0] = *(unsigned*)&Wh[n0 * AST + k0 + q * 2];
                bh[n][1] = *(unsigned*)&Wh[n0 * AST + k0 + 8 + q * 2];
                bl[n][0] = *(unsigned*)&Wl[n0 * AST + k0 + q * 2];
                bl[n][1] = *(unsigned*)&Wl[n0 * AST + k0 + 8 + q * 2];
            }
#pragma unroll
            for (int m = 0; m < 2; m++)
#pragma unroll
                for (int n = 0; n < 8; n++) {
                    mma16816f16(c[m * 8 + n], a[m], bh[n]);
                    mma16816f16(c[m * 8 + n], a[m], bl[n]);
                }
        }

        // epilogue: bias, store (fp16 or fp32), fused output column stats
#pragma unroll
        for (int n = 0; n < 8; n++) {
            int col = wc + n * 8 + q * 2;
            float b0 = bias_s[col], b1 = bias_s[col + 1];
            float s0 = 0.f, s1 = 0.f, q0 = 0.f, q1 = 0.f;
#pragma unroll
            for (int m = 0; m < 2; m++) {
                int row0 = ti * 128 + wr + m * 16 + g;
                float* cf = c[m * 8 + n];
                float v0 = cf[0] + b0, v1 = cf[1] + b1;
                float v2 = cf[2] + b0, v3 = cf[3] + b1;
                if (row0 < NND) {
                    if (outFp16) {
                        __half2 h = __floats2half2_rn(v0, v1);
                        ((unsigned*)Zout)[(size_t)row0 * 64 + (col >> 1)] = *(unsigned*)&h;
                    } else {
                        *(float2*)((float*)Zout + (size_t)row0 * DD + col) = make_float2(v0, v1);
                    }
                    s0 += v0; s1 += v1; q0 += v0 * v0; q1 += v1 * v1;
                }
                if (row0 + 8 < NND) {
                    if (outFp16) {
                        __half2 h = __floats2half2_rn(v2, v3);
                        ((unsigned*)Zout)[(size_t)(row0 + 8) * 64 + (col >> 1)] = *(unsigned*)&h;
                    } else {
                        *(float2*)((float*)Zout + (size_t)(row0 + 8) * DD + col) = make_float2(v2, v3);
                    }
                    s0 += v2; s1 += v3; q0 += v2 * v2; q1 += v3 * v3;
                }
            }
#pragma unroll
            for (int o = 4; o < 32; o <<= 1) {
                s0 += __shfl_xor_sync(0xffffffffu, s0, o);
                s1 += __shfl_xor_sync(0xffffffffu, s1, o);
                q0 += __shfl_xor_sync(0xffffffffu, q0, o);
                q1 += __shfl_xor_sync(0xffffffffu, q1, o);
            }
            if (lane < 4) {
                atomicAdd(&colsum[col], s0);
                atomicAdd(&colsum[col + 1], s1);
                atomicAdd(&colsq[col], q0);
                atomicAdd(&colsq[col + 1], q1);
            }
        }
    }

    __syncthreads();
    if (t < DD) {
        atomicAdd(&statsOut[t], colsum[t]);
        atomicAdd(&statsOut[DD + t], colsq[t]);
    }
}

// ---------------- BN-on-the-fly segmented pooling + fp16 image write ----------------
__global__ void k_pool(float* __restrict__ pg, const float* __restrict__ Z,
                       const float* __restrict__ gam, const float* __restrict__ bet,
                       const float* __restrict__ stats, const int* __restrict__ gids,
                       unsigned short* __restrict__ H16, int writeH) {
    __shared__ float sc[DD], sh[DD];
    int t = threadIdx.x;
    if (t < DD) {
        const float inv_n = 1.0f / (float)NND;
        float mu = stats[t] * inv_n;
        float var = stats[DD + t] * inv_n - mu * mu;
        float s = __ldg(&gam[t]) * rsqrtf(var + BN_EPS);
        sc[t] = s;
        sh[t] = __ldg(&bet[t]) - mu * s;
    }
    __syncthreads();
    int warp = (blockIdx.x * blockDim.x + t) >> 5;
    int lane = t & 31;
    int r0 = warp * 32;
    if (r0 >= NND) return;
    int r1 = min(r0 + 32, NND);
    int ch = lane * 4;
    float c0 = sc[ch], c1 = sc[ch + 1], c2 = sc[ch + 2], c3 = sc[ch + 3];
    float h0 = sh[ch], h1 = sh[ch + 1], h2 = sh[ch + 2], h3 = sh[ch + 3];
    int cur = __ldg(&gids[r0]);
    float4 acc = make_float4(0.f, 0.f, 0.f, 0.f);
    for (int r = r0; r < r1; r++) {
        int gid = __ldg(&gids[r]);
        if (gid != cur) {
            red_add_v4(&pg[cur * DD + ch], acc);
            acc = make_float4(0.f, 0.f, 0.f, 0.f);
            cur = gid;
        }
        float4 v = ((const float4*)Z)[r * 32 + lane];
        float4 a;
        a.x = fmaxf(v.x * c0 + h0, 0.f);
        a.y = fmaxf(v.y * c1 + h1, 0.f);
        a.z = fmaxf(v.z * c2 + h2, 0.f);
        a.w = fmaxf(v.w * c3 + h3, 0.f);
        if (writeH) ((uint2*)H16)[(size_t)r * 32 + lane] = pack_h4(a);
        acc.x += a.x; acc.y += a.y; acc.z += a.z; acc.w += a.w;
    }
    red_add_v4(&pg[cur * DD + ch], acc);
}

// segmented pooling for layer-0 (h = x) + fp16 image of x
__global__ void k_gpool(float* __restrict__ pg, const float* __restrict__ h,
                        const int* __restrict__ gids, unsigned short* __restrict__ H16) {
    int warp = (blockIdx.x * blockDim.x + threadIdx.x) >> 5;
    int lane = threadIdx.x & 31;
    int r0 = warp * 32;
    if (r0 >= NND) return;
    int r1 = min(r0 + 32, NND);
    int ch = lane * 4;
    int cur = __ldg(&gids[r0]);
    float4 acc = make_float4(0.f, 0.f, 0.f, 0.f);
    for (int r = r0; r < r1; r++) {
        int gid = __ldg(&gids[r]);
        if (gid != cur) {
            red_add_v4(&pg[cur * DD + ch], acc);
            acc = make_float4(0.f, 0.f, 0.f, 0.f);
            cur = gid;
        }
        float4 v = ((const float4*)h)[r * 32 + lane];
        ((uint2*)H16)[(size_t)r * 32 + lane] = pack_h4(v);
        acc.x += v.x; acc.y += v.y; acc.z += v.z; acc.w += v.w;
    }
    red_add_v4(&pg[cur * DD + ch], acc);
}

__global__ void k_readout(float* __restrict__ out,
                          const float* __restrict__ predW,
                          const float* __restrict__ predb) {
    int g = blockIdx.x;
    int o = threadIdx.x;
    float acc = 0.f;
#pragma unroll
    for (int l = 0; l < NL + 1; l++) {
        const float* pgrow = &g_pg[l * NG * DD + g * DD];
        const float* Wl = &predW[l * DD * OUTD];
        float a = 0.f;
        for (int k = 0; k < DD; k++)
            a += pgrow[k] * __ldg(&Wl[k * OUTD + o]);
        acc += a + __ldg(&predb[l * OUTD + o]);
    }
    out[g * OUTD + o] = acc;
}

// ---------------- launch ----------------
extern "C" void kernel_launch(void* const* d_in, const int* in_sizes, int n_in,
                              void* d_out, int out_size) {
    const float* x     = (const float*)d_in[0];
    const int* esrc    = (const int*)d_in[1];
    const int* edst    = (const int*)d_in[2];
    const int* gids    = (const int*)d_in[3];
    const float* eps   = (const float*)d_in[4];
    const float* W1    = (const float*)d_in[5];
    const float* b1    = (const float*)d_in[6];
    const float* g1    = (const float*)d_in[7];
    const float* be1   = (const float*)d_in[8];
    const float* W2    = (const float*)d_in[9];
    const float* b2    = (const float*)d_in[10];
    const float* g2    = (const float*)d_in[11];
    const float* be2   = (const float*)d_in[12];
    const float* predW = (const float*)d_in[13];
    const float* predb = (const float*)d_in[14];
    float* out = (float*)d_out;

    float *Pf, *Zf, *Z2, *stats, *pg;
    unsigned short* H16;
    int* deg;
    cudaGetSymbolAddress((void**)&Pf, g_P);
    cudaGetSymbolAddress((void**)&Zf, g_Z);
    cudaGetSymbolAddress((void**)&Z2, g_Z2);
    cudaGetSymbolAddress((void**)&H16, g_H16);
    cudaGetSymbolAddress((void**)&stats, g_stats);
    cudaGetSymbolAddress((void**)&pg, g_pg);
    cudaGetSymbolAddress((void**)&deg, g_deg);
    unsigned short* P16 = (unsigned short*)Pf;
    unsigned short* Z16 = (unsigned short*)Zf;
    float* s0 = stats;
    float* s1 = stats + 2 * DD;

    const int smem_mm = 3 * DD * AST * (int)sizeof(unsigned short) + 32768;  // 134144
    static bool attr_set = false;
    if (!attr_set) {
        cudaFuncSetAttribute(k_mm, cudaFuncAttributeMaxDynamicSharedMemorySize, smem_mm);
        attr_set = true;
    }

    const int gridEdge = (NE + 255) / 256;
    const int nWarps = (NND + 31) / 32;
    const int gridSeg = (nWarps * 32 + 255) / 256;

    // CSR build (once; shared by all 4 layers)
    cudaMemsetAsync(deg, 0, sizeof(int) * NND);
    k_hist<<<gridEdge, 256>>>(edst);
    k_scan<<<1, 1024>>>();
    k_scatter<<<gridEdge, 256>>>(esrc, edst);

    // layer-0 graph pooling + fp16 image of x
    cudaMemsetAsync(pg, 0, sizeof(float) * (NL + 1) * NG * DD);
    k_gpool<<<gridSeg, 256>>>(pg, x, gids, H16);

    for (int l = 0; l < NL; l++) {
        k_agg<<<(NND + 7) / 8, 256>>>(P16, H16, eps, l);

        cudaMemsetAsync(s0, 0, sizeof(float) * 2 * DD);
        k_mm<<<148, 256, smem_mm>>>(Z16, P16, W1 + l * DD * DD, b1 + l * DD,
                                    nullptr, nullptr, nullptr, s0, 1);

        cudaMemsetAsync(s1, 0, sizeof(float) * 2 * DD);
        k_mm<<<148, 256, smem_mm>>>(Z2, Z16, W2 + l * DD * DD, b2 + l * DD,
                                    g1 + l * DD, be1 + l * DD, s0, s1, 0);

        k_pool<<<gridSeg, 256>>>(pg + (l + 1) * NG * DD, Z2,
                                 g2 + l * DD, be2 + l * DD, s1, gids,
                                 H16, l < NL - 1 ? 1 : 0);
    }

    k_readout<<<NG, OUTD>>>(out, predW, predb);
}